// round 14
// baseline (speedup 1.0000x reference)
#include <cuda_runtime.h>
#include <cuda_fp16.h>
#include <math.h>

#define L_ 4
#define H_ 12
#define E_ 768
#define T_ 1024
#define B_ 4
#define V_ 50257
#define D_ 64
#define M_ (B_*T_)     // 4096
#define E3_ (3*E_)     // 2304
#define E4_ (4*E_)     // 3072
#define NBN_V ((V_ + 127) >> 7)   // 393

// ---------------- scratch (static device globals; no allocation) ----------
__device__ float  g_x  [(size_t)M_*E_];
__device__ __half g_h  [(size_t)M_*E_];
__device__ float  g_qkv[(size_t)M_*E3_];
__device__ __half g_y  [(size_t)M_*E_];
__device__ __half g_fc [(size_t)M_*E4_];
__device__ float  g_logp[B_*(T_-1)];
__device__ float  g_lpart[(size_t)M_*NBN_V*2];
// fp16 weight copies (converted once per launch)
__device__ __half g_w_attn[(size_t)L_*E3_*E_];
__device__ __half g_w_proj[(size_t)L_*E_*E_];
__device__ __half g_w_fc  [(size_t)L_*E4_*E_];
__device__ __half g_w_out [(size_t)L_*E_*E4_];
__device__ __half g_w_wte [(size_t)V_*E_];

// ---------------- reductions ----------------------------------------------
__device__ __forceinline__ float blockReduceSum(float v, float* red) {
    int lane = threadIdx.x & 31, wid = threadIdx.x >> 5;
    #pragma unroll
    for (int o = 16; o; o >>= 1) v += __shfl_down_sync(0xffffffffu, v, o);
    __syncthreads();
    if (lane == 0) red[wid] = v;
    __syncthreads();
    if (threadIdx.x == 0) {
        float s = 0.f;
        int nw = (blockDim.x + 31) >> 5;
        for (int i = 0; i < nw; i++) s += red[i];
        red[0] = s;
    }
    __syncthreads();
    return red[0];
}

// ---------------- mma / ldmatrix helpers ------------------------------------
#define MMA_F16(acc, a0,a1,a2,a3, b0,b1)                                    \
    asm volatile(                                                            \
        "mma.sync.aligned.m16n8k16.row.col.f32.f16.f16.f32 "                \
        "{%0,%1,%2,%3}, {%4,%5,%6,%7}, {%8,%9}, {%0,%1,%2,%3};"             \
        : "+f"((acc)[0]), "+f"((acc)[1]), "+f"((acc)[2]), "+f"((acc)[3])    \
        : "r"(a0), "r"(a1), "r"(a2), "r"(a3), "r"(b0), "r"(b1))

#define LDSM_X4(r0,r1,r2,r3, addr)                                          \
    asm volatile(                                                            \
        "ldmatrix.sync.aligned.m8n8.x4.shared.b16 {%0,%1,%2,%3}, [%4];"     \
        : "=r"(r0), "=r"(r1), "=r"(r2), "=r"(r3) : "r"(addr))

#define LDSM_X4T(r0,r1,r2,r3, addr)                                         \
    asm volatile(                                                            \
        "ldmatrix.sync.aligned.m8n8.x4.trans.shared.b16 {%0,%1,%2,%3}, [%4];" \
        : "=r"(r0), "=r"(r1), "=r"(r2), "=r"(r3) : "r"(addr))

__device__ __forceinline__ unsigned smem_u32(const void* p) {
    unsigned a;
    asm("{ .reg .u64 t; cvta.to.shared.u64 t, %1; cvt.u32.u64 %0, t; }"
        : "=r"(a) : "l"(p));
    return a;
}

// split fp32 -> hi/lo fp16 and store a float4 into swizzled [row][64] tiles
__device__ __forceinline__ void store_split4(__half* hb, __half* lb,
                                             int row, int c, float4 v) {
    int ph = row * 64 + (((c >> 3) ^ (row & 7)) << 3) + (c & 7);
    __half h0 = __float2half_rn(v.x), h1 = __float2half_rn(v.y);
    __half h2 = __float2half_rn(v.z), h3 = __float2half_rn(v.w);
    *(__half2*)(hb + ph)     = __halves2half2(h0, h1);
    *(__half2*)(hb + ph + 2) = __halves2half2(h2, h3);
    *(__half2*)(lb + ph)     = __halves2half2(
        __float2half_rn(v.x - __half2float(h0)),
        __float2half_rn(v.y - __half2float(h1)));
    *(__half2*)(lb + ph + 2) = __halves2half2(
        __float2half_rn(v.z - __half2float(h2)),
        __float2half_rn(v.w - __half2float(h3)));
}

// ---------------- weight fp16 conversion -----------------------------------
__global__ void cvt_f16_kernel(const float4* __restrict__ in,
                               __half2* __restrict__ out, int n4) {
    int i = blockIdx.x * 256 + threadIdx.x;
    if (i < n4) {
        float4 v = in[i];
        out[2 * i]     = __floats2half2_rn(v.x, v.y);
        out[2 * i + 1] = __floats2half2_rn(v.z, v.w);
    }
}

// ---------------- embedding -----------------------------------------------
__global__ void embed_kernel(const int* __restrict__ idx,
                             const float* __restrict__ wte,
                             const float* __restrict__ wpe) {
    int i = blockIdx.x * 256 + threadIdx.x;
    int bt = i / E_, e = i - bt * E_;
    int t = bt & (T_ - 1);
    g_x[i] = wte[(size_t)idx[bt] * E_ + e] + wpe[(size_t)t * E_ + e];
}

// ---------------- layernorm: warp per row, fp16 output ----------------------
__global__ __launch_bounds__(256)
void ln_kernel(const float* __restrict__ in,
               const float* __restrict__ w,
               const float* __restrict__ b,
               __half* __restrict__ out) {
    int wid = threadIdx.x >> 5, lane = threadIdx.x & 31;
    int row = blockIdx.x * 8 + wid;
    const float4* x4 = (const float4*)(in + (size_t)row * E_);
    float4 v[6];
    float s = 0.f;
    #pragma unroll
    for (int i = 0; i < 6; i++) {
        v[i] = x4[lane + i * 32];
        s += v[i].x + v[i].y + v[i].z + v[i].w;
    }
    #pragma unroll
    for (int o = 16; o; o >>= 1) s += __shfl_xor_sync(0xffffffffu, s, o);
    float m = s * (1.0f / E_);
    float var = 0.f;
    #pragma unroll
    for (int i = 0; i < 6; i++) {
        float dx = v[i].x - m, dy = v[i].y - m, dz = v[i].z - m, dw = v[i].w - m;
        var += dx * dx + dy * dy + dz * dz + dw * dw;
    }
    #pragma unroll
    for (int o = 16; o; o >>= 1) var += __shfl_xor_sync(0xffffffffu, var, o);
    float r = rsqrtf(var * (1.0f / E_) + 1e-5f);
    __half* o = out + (size_t)row * E_;
    #pragma unroll
    for (int i = 0; i < 6; i++) {
        int c = (lane + i * 32) * 4;
        float4 w4 = ((const float4*)w)[lane + i * 32];
        float4 b4 = ((const float4*)b)[lane + i * 32];
        float o0 = (v[i].x - m) * r * w4.x + b4.x;
        float o1 = (v[i].y - m) * r * w4.y + b4.y;
        float o2 = (v[i].z - m) * r * w4.z + b4.z;
        float o3 = (v[i].w - m) * r * w4.w + b4.w;
        *(__half2*)(o + c)     = __floats2half2_rn(o0, o1);
        *(__half2*)(o + c + 2) = __floats2half2_rn(o2, o3);
    }
}

// ---------------- FP16 GEMM: C = A[MxK] * B[NxK]^T --------------------------
// Block tile 256x128x64, 512 threads, 16 warps (4m x 4n), warp tile 64x32.
// 3-stage cp.async, XOR-swizzled smem. Higher arithmetic intensity vs 128x128.
#define GSTAGES 3
#define ASTG (256 * 64)                 // halves per A stage
#define BSTG (128 * 64)                 // halves per B stage
#define GEMM_SMEM (GSTAGES * (ASTG + BSTG) * 2)   // 147456 bytes

__global__ __launch_bounds__(512, 1)
void gemm_f16(const __half* __restrict__ A, const __half* __restrict__ B,
              const float* __restrict__ bias, const float* __restrict__ res,
              float* __restrict__ C, __half* __restrict__ Ch,
              float* __restrict__ lpart,
              int M, int N, int K, int gelu) {
    extern __shared__ __half hsm[];
    __half* As = hsm;
    __half* Bs = hsm + GSTAGES * ASTG;

    int nbn = (N + 127) >> 7;
    int bid = blockIdx.x;
    int bpg = 4 * nbn;                  // 4 m-rows per L2 group
    int grp = bid / bpg, rr = bid % bpg;
    int m0 = (grp * 4 + (rr & 3)) << 8;
    int n0 = (rr >> 2) << 7;

    int tid = threadIdx.x;
    int lane = tid & 31, wid = tid >> 5;
    int wm = wid >> 2, wn = wid & 3;    // 4m x 4n warps
    int la = lane & 3, lg = lane >> 2;

    // cp.async mapping: rows of 64 halves (8 chunks of 16B), swizzle c^(row&7)
    int r0 = tid >> 3, c0 = tid & 7;    // r0: 0..63
    int off0 = r0 * 64 + ((c0 ^ (r0 & 7)) << 3);
    const __half* aBase = A + (size_t)(m0 + r0) * K + c0 * 8;   // +64-row steps
    const __half* bP[2]; int bok[2];
    #pragma unroll
    for (int i = 0; i < 2; i++) {
        int bn = n0 + r0 + 64 * i;
        bok[i] = (bn < N) ? 16 : 0;
        bP[i] = B + (size_t)(bok[i] ? bn : 0) * K + c0 * 8;
    }
    unsigned sAb = smem_u32(As), sBb = smem_u32(Bs);

    auto issue = [&](int st, int kb) {
        unsigned ab = sAb + (unsigned)(st * ASTG + off0) * 2u;
        unsigned bb = sBb + (unsigned)(st * BSTG + off0) * 2u;
        #pragma unroll
        for (int i = 0; i < 4; i++) {   // A: 4 x 64 rows
            asm volatile("cp.async.cg.shared.global [%0], [%1], 16;"
                         :: "r"(ab + i * 8192u), "l"(aBase + (size_t)i * 64 * K + kb));
        }
        #pragma unroll
        for (int i = 0; i < 2; i++) {   // B: 2 x 64 rows
            asm volatile("cp.async.cg.shared.global [%0], [%1], 16, %2;"
                         :: "r"(bb + i * 8192u), "l"(bP[i] + kb), "r"(bok[i]));
        }
    };

    int l7 = lane & 7;
    unsigned aRow[4];
    #pragma unroll
    for (int mt = 0; mt < 4; mt++)
        aRow[mt] = (unsigned)((wm * 64 + mt * 16 + l7 + ((lane >> 3) & 1) * 8) * 128);
    int aCx = lane >> 4;
    unsigned bRow[2];
    #pragma unroll
    for (int p = 0; p < 2; p++)
        bRow[p] = (unsigned)((wn * 32 + p * 16 + l7 + (lane >> 4) * 8) * 128);
    int bCx = (lane >> 3) & 1;

    float acc[4][4][4];
    #pragma unroll
    for (int i = 0; i < 4; i++)
        #pragma unroll
        for (int j = 0; j < 4; j++)
            #pragma unroll
            for (int k = 0; k < 4; k++) acc[i][j][k] = 0.f;

    int nk = K >> 6;
    issue(0, 0);  asm volatile("cp.async.commit_group;");
    issue(1, 64); asm volatile("cp.async.commit_group;");

    int cst = 0, pst = 2;
    for (int kt = 0; kt < nk; kt++) {
        asm volatile("cp.async.wait_group 1;");
        __syncthreads();
        int pf = kt + 2;
        if (pf < nk) issue(pst, pf << 6);
        asm volatile("cp.async.commit_group;");
        if (++pst == GSTAGES) pst = 0;

        unsigned aS = sAb + (unsigned)(cst * ASTG) * 2u;
        unsigned bS = sBb + (unsigned)(cst * BSTG) * 2u;
        if (++cst == GSTAGES) cst = 0;

        #pragma unroll
        for (int ks = 0; ks < 4; ks++) {
            unsigned af[4][4], bf[4][2];
            #pragma unroll
            for (int mt = 0; mt < 4; mt++) {
                unsigned ad = aS + aRow[mt] + (unsigned)((((2 * ks + aCx) ^ l7)) << 4);
                LDSM_X4(af[mt][0], af[mt][1], af[mt][2], af[mt][3], ad);
            }
            #pragma unroll
            for (int p = 0; p < 2; p++) {
                unsigned bd = bS + bRow[p] + (unsigned)((((2 * ks + bCx) ^ l7)) << 4);
                LDSM_X4(bf[2*p][0], bf[2*p][1], bf[2*p+1][0], bf[2*p+1][1], bd);
            }
            #pragma unroll
            for (int mt = 0; mt < 4; mt++)
                #pragma unroll
                for (int nt = 0; nt < 4; nt++)
                    MMA_F16(acc[mt][nt], af[mt][0], af[mt][1], af[mt][2], af[mt][3],
                            bf[nt][0], bf[nt][1]);
        }
    }

    if (bias) {
        #pragma unroll
        for (int nt = 0; nt < 4; nt++) {
            int cb = n0 + wn * 32 + nt * 8 + la * 2;
            float b0 = (cb < N)     ? bias[cb]     : 0.f;
            float b1 = (cb + 1 < N) ? bias[cb + 1] : 0.f;
            #pragma unroll
            for (int mt = 0; mt < 4; mt++) {
                acc[mt][nt][0] += b0; acc[mt][nt][1] += b1;
                acc[mt][nt][2] += b0; acc[mt][nt][3] += b1;
            }
        }
    }

    #pragma unroll
    for (int mt = 0; mt < 4; mt++) {
        int rbase = m0 + wm * 64 + mt * 16 + lg;
        #pragma unroll
        for (int nt = 0; nt < 4; nt++) {
            int cbase = n0 + wn * 32 + nt * 8 + la * 2;
            #pragma unroll
            for (int hf = 0; hf < 2; hf++) {
                int rw = rbase + hf * 8;
                #pragma unroll
                for (int cc = 0; cc < 2; cc++) {
                    int c = cbase + cc;
                    if (c < N) {
                        float v = acc[mt][nt][hf * 2 + cc];
                        if (gelu) {
                            float u = v;
                            float w = 0.7978845608028654f * (u + 0.044715f * u * u * u);
                            v = u / (1.0f + __expf(-2.0f * w));
                        }
                        size_t off = (size_t)rw * N + c;
                        if (Ch) {
                            Ch[off] = __float2half_rn(v);
                        } else {
                            if (res) v += res[off];
                            C[off] = v;
                        }
                    }
                }
            }
        }
    }

    if (lpart) {
        asm volatile("cp.async.wait_group 0;");
        __syncthreads();
        float* red = (float*)hsm;               // [256 rows][4 wn][2] = 8KB
        #pragma unroll
        for (int mt = 0; mt < 4; mt++) {
            #pragma unroll
            for (int hf = 0; hf < 2; hf++) {
                int wrow = wm * 64 + mt * 16 + lg + hf * 8;
                float vmax = -1e30f;
                #pragma unroll
                for (int nt = 0; nt < 4; nt++)
                    #pragma unroll
                    for (int cc = 0; cc < 2; cc++) {
                        int c = n0 + wn * 32 + nt * 8 + la * 2 + cc;
                        if (c < N) vmax = fmaxf(vmax, acc[mt][nt][hf * 2 + cc]);
                    }
                vmax = fmaxf(vmax, __shfl_xor_sync(0xffffffffu, vmax, 1));
                vmax = fmaxf(vmax, __shfl_xor_sync(0xffffffffu, vmax, 2));
                float vsum = 0.f;
                #pragma unroll
                for (int nt = 0; nt < 4; nt++)
                    #pragma unroll
                    for (int cc = 0; cc < 2; cc++) {
                        int c = n0 + wn * 32 + nt * 8 + la * 2 + cc;
                        if (c < N) vsum += __expf(acc[mt][nt][hf * 2 + cc] - vmax);
                    }
                vsum += __shfl_xor_sync(0xffffffffu, vsum, 1);
                vsum += __shfl_xor_sync(0xffffffffu, vsum, 2);
                if (la == 0) {
                    red[(wrow * 4 + wn) * 2]     = vmax;
                    red[(wrow * 4 + wn) * 2 + 1] = vsum;
                }
            }
        }
        __syncthreads();
        if (tid < 256) {
            float Mv = -1e30f, Sv = 0.f;
            #pragma unroll
            for (int w = 0; w < 4; w++) {
                float mi = red[(tid * 4 + w) * 2];
                float si = red[(tid * 4 + w) * 2 + 1];
                if (mi > Mv) { Sv = Sv * __expf(Mv - mi) + si; Mv = mi; }
                else         { Sv += si * __expf(mi - Mv); }
            }
            size_t pidx = ((size_t)(m0 + tid) * nbn + (n0 >> 7)) * 2;
            lpart[pidx]     = Mv;
            lpart[pidx + 1] = Sv;
        }
    }
}

// ---------------- flash attention v2 (R11) + LPT block ordering -------------
#define FQ 128
#define FATT_SMEM (49152 * 2)

__global__ __launch_bounds__(256)
void flash_attn(const float* __restrict__ qkv, __half* __restrict__ y) {
    extern __shared__ __half fh[];
    __half *Qh = fh,          *Ql = fh + 8192;
    __half *Kh = fh + 16384,  *Kl = fh + 20480;
    __half *Vh = fh + 24576,  *Vl = fh + 28672;
    __half *Ph = fh + 32768,  *Pl = fh + 40960;

    int bh = blockIdx.y;
    int b = bh / H_, h = bh % H_;
    int q0 = ((int)gridDim.x - 1 - (int)blockIdx.x) * FQ;
    int tid = threadIdx.x;
    int lane = tid & 31, wid = tid >> 5;
    int la = lane & 3, lg = lane >> 2;
    int l7 = lane & 7;

    unsigned sb = smem_u32(fh);
    unsigned sQh = sb, sQl = sb + 16384;
    unsigned sKh = sb + 32768, sKl = sb + 40960;
    unsigned sVh = sb + 49152, sVl = sb + 57344;
    unsigned sPh = sb + 65536, sPl = sb + 81920;

    #pragma unroll
    for (int i = 0; i < 8; i++) {
        int f4 = tid + i * 256;
        int row = f4 >> 4, c = (f4 & 15) << 2;
        float4 v = *(const float4*)(qkv + (size_t)(b * T_ + q0 + row) * E3_ + h * D_ + c);
        store_split4(Qh, Ql, row, c, v);
    }
    __syncthreads();

    int aCx = lane >> 4;
    unsigned qRowOff = (unsigned)((wid * 16 + l7 + ((lane >> 3) & 1) * 8) * 128);
    unsigned qfh[4][4], qfl[4][4];
    #pragma unroll
    for (int kc = 0; kc < 4; kc++) {
        unsigned cx = (unsigned)((((2 * kc + aCx) ^ l7)) << 4);
        LDSM_X4(qfh[kc][0], qfh[kc][1], qfh[kc][2], qfh[kc][3], sQh + qRowOff + cx);
        LDSM_X4(qfl[kc][0], qfl[kc][1], qfl[kc][2], qfl[kc][3], sQl + qRowOff + cx);
    }

    float m0r = -1e30f, m1r = -1e30f, l0r = 0.f, l1r = 0.f;
    float acc_o[8][4];
    #pragma unroll
    for (int i = 0; i < 8; i++)
        #pragma unroll
        for (int j = 0; j < 4; j++) acc_o[i][j] = 0.f;

    int row0g = q0 + wid * 16 + lg;
    int row1g = row0g + 8;
    int lastNeeded = (q0 + wid * 16 + 15) >> 6;
    int nkt = (q0 >> 6) + 2;

    for (int kt = 0; kt < nkt; kt++) {
        int k0 = kt << 6;
        __syncthreads();
        #pragma unroll
        for (int i = 0; i < 4; i++) {
            int f4 = tid + i * 256;
            int row = f4 >> 4, c = (f4 & 15) << 2;
            const float* base = qkv + (size_t)(b * T_ + k0 + row) * E3_ + h * D_ + c;
            float4 kv = *(const float4*)(base + E_);
            float4 vv = *(const float4*)(base + 2 * E_);
            store_split4(Kh, Kl, row, c, kv);
            store_split4(Vh, Vl, row, c, vv);
        }
        __syncthreads();
        if (kt > lastNeeded) continue;

        float s[8][4];
        #pragma unroll
        for (int i = 0; i < 8; i++)
            #pragma unroll
            for (int j = 0; j < 4; j++) s[i][j] = 0.f;

        int bCx = (lane >> 3) & 1;
        #pragma unroll
        for (int kc = 0; kc < 4; kc++) {
            unsigned kfh[8][2], kfl[8][2];
            #pragma unroll
            for (int p = 0; p < 4; p++) {
                unsigned rOff = (unsigned)((p * 16 + l7 + ((lane >> 4) << 3)) * 128);
                unsigned cx = (unsigned)((((2 * kc + bCx) ^ l7)) << 4);
                LDSM_X4(kfh[2*p][0], kfh[2*p][1], kfh[2*p+1][0], kfh[2*p+1][1],
                        sKh + rOff + cx);
                LDSM_X4(kfl[2*p][0], kfl[2*p][1], kfl[2*p+1][0], kfl[2*p+1][1],
                        sKl + rOff + cx);
            }
            #pragma unroll
            for (int nt = 0; nt < 8; nt++) {
                MMA_F16(s[nt], qfl[kc][0], qfl[kc][1], qfl[kc][2], qfl[kc][3],
                        kfh[nt][0], kfh[nt][1]);
                MMA_F16(s[nt], qfh[kc][0], qfh[kc][1], qfh[kc][2], qfh[kc][3],
                        kfl[nt][0], kfl[nt][1]);
                MMA_F16(s[nt], qfh[kc][0], qfh[kc][1], qfh[kc][2], qfh[kc][3],
                        kfh[nt][0], kfh[nt][1]);
            }
        }

        #pragma unroll
        for (int nt = 0; nt < 8; nt++) {
            int c0c = k0 + nt * 8 + 2 * la;
            s[nt][0] = (c0c     <= row0g) ? s[nt][0] * 0.125f : -1e30f;
            s[nt][1] = (c0c + 1 <= row0g) ? s[nt][1] * 0.125f : -1e30f;
            s[nt][2] = (c0c     <= row1g) ? s[nt][2] * 0.125f : -1e30f;
            s[nt][3] = (c0c + 1 <= row1g) ? s[nt][3] * 0.125f : -1e30f;
        }

        float mx0 = -1e30f, mx1 = -1e30f;
        #pragma unroll
        for (int nt = 0; nt < 8; nt++) {
            mx0 = fmaxf(mx0, fmaxf(s[nt][0], s[nt][1]));
            mx1 = fmaxf(mx1, fmaxf(s[nt][2], s[nt][3]));
        }
        mx0 = fmaxf(mx0, __shfl_xor_sync(0xffffffffu, mx0, 1));
        mx0 = fmaxf(mx0, __shfl_xor_sync(0xffffffffu, mx0, 2));
        mx1 = fmaxf(mx1, __shfl_xor_sync(0xffffffffu, mx1, 1));
        mx1 = fmaxf(mx1, __shfl_xor_sync(0xffffffffu, mx1, 2));
        float m0n = fmaxf(m0r, mx0), m1n = fmaxf(m1r, mx1);
        float a0 = __expf(m0r - m0n), a1 = __expf(m1r - m1n);
        m0r = m0n; m1r = m1n;

        float ts0 = 0.f, ts1 = 0.f;
        #pragma unroll
        for (int nt = 0; nt < 8; nt++) {
            s[nt][0] = __expf(s[nt][0] - m0n);
            s[nt][1] = __expf(s[nt][1] - m0n);
            s[nt][2] = __expf(s[nt][2] - m1n);
            s[nt][3] = __expf(s[nt][3] - m1n);
            ts0 += s[nt][0] + s[nt][1];
            ts1 += s[nt][2] + s[nt][3];
        }
        ts0 += __shfl_xor_sync(0xffffffffu, ts0, 1);
        ts0 += __shfl_xor_sync(0xffffffffu, ts0, 2);
        ts1 += __shfl_xor_sync(0xffffffffu, ts1, 1);
        ts1 += __shfl_xor_sync(0xffffffffu, ts1, 2);
        l0r = l0r * a0 + ts0;
        l1r = l1r * a1 + ts1;
        #pragma unroll
        for (int nt = 0; nt < 8; nt++) {
            acc_o[nt][0] *= a0; acc_o[nt][1] *= a0;
            acc_o[nt][2] *= a1; acc_o[nt][3] *= a1;
        }

        __half* Pwh = Ph + wid * 1024;
        __half* Pwl = Pl + wid * 1024;
        #pragma unroll
        for (int nt = 0; nt < 8; nt++) {
            int ph0 = lg * 64 + ((nt ^ (lg & 7)) << 3) + 2 * la;
            __half h0 = __float2half_rn(s[nt][0]), h1 = __float2half_rn(s[nt][1]);
            *(__half2*)(Pwh + ph0) = __halves2half2(h0, h1);
            *(__half2*)(Pwl + ph0) = __halves2half2(
                __float2half_rn(s[nt][0] - __half2float(h0)),
                __float2half_rn(s[nt][1] - __half2float(h1)));
            int ph1 = ph0 + 8 * 64;
            __half h2 = __float2half_rn(s[nt][2]), h3 = __float2half_rn(s[nt][3]);
            *(__half2*)(Pwh + ph1) = __halves2half2(h2, h3);
            *(__half2*)(Pwl + ph1) = __halves2half2(
                __float2half_rn(s[nt][2] - __half2float(h2)),
                __float2half_rn(s[nt][3] - __half2float(h3)));
        }
        __syncwarp();

        unsigned pRowOff = (unsigned)((l7 + ((lane >> 3) & 1) * 8) * 128)
                         + (unsigned)(wid * 2048);
        #pragma unroll
        for (int kc = 0; kc < 4; kc++) {
            unsigned pfh[4], pfl[4];
            unsigned cx = (unsigned)((((2 * kc + aCx) ^ l7)) << 4);
            LDSM_X4(pfh[0], pfh[1], pfh[2], pfh[3], sPh + pRowOff + cx);
            LDSM_X4(pfl[0], pfl[1], pfl[2], pfl[3], sPl + pRowOff + cx);
            unsigned vfh[8][2], vfl[8][2];
            int vrow = kc * 16 + l7 + ((lane >> 3) & 1) * 8;
            #pragma unroll
            for (int pd = 0; pd < 4; pd++) {
                int dgc = 2 * pd + (lane >> 4);
                unsigned voff = (unsigned)(vrow * 128 + (((dgc) ^ (vrow & 7)) << 4));
                LDSM_X4T(vfh[2*pd][0], vfh[2*pd][1], vfh[2*pd+1][0], vfh[2*pd+1][1],
                         sVh + voff);
                LDSM_X4T(vfl[2*pd][0], vfl[2*pd][1], vfl[2*pd+1][0], vfl[2*pd+1][1],
                         sVl + voff);
            }
            #pragma unroll
            for (int nt = 0; nt < 8; nt++) {
                MMA_F16(acc_o[nt], pfl[0], pfl[1], pfl[2], pfl[3],
                        vfh[nt][0], vfh[nt][1]);
                MMA_F16(acc_o[nt], pfh[0], pfh[1], pfh[2], pfh[3],
                        vfl[nt][0], vfl[nt][1]);
                MMA_F16(acc_o[nt], pfh[0], pfh[1], pfh[2], pfh[3],
                        vfh[nt][0], vfh[nt][1]);
            }
        }
    }

    float inv0 = 1.0f / l0r, inv1 = 1.0f / l1r;
    size_t o0 = (size_t)(b * T_ + q0 + wid * 16 + lg) * E_ + h * D_;
    size_t o1 = o0 + 8 * E_;
    #pragma unroll
    for (int nt = 0; nt < 8; nt++) {
        int c = nt * 8 + 2 * la;
        *(__half2*)(y + o0 + c) = __floats2half2_rn(acc_o[nt][0] * inv0,
                                                    acc_o[nt][1] * inv0);
        *(__half2*)(y + o1 + c) = __floats2half2_rn(acc_o[nt][2] * inv1,
                                                    acc_o[nt][3] * inv1);
    }
}

// ---------------- loss: combine per-block partials (one warp per row) -------
__global__ __launch_bounds__(256)
void loss_reduce(const float* __restrict__ logits,
                 const int* __restrict__ targets) {
    int gid = blockIdx.x * 8 + (threadIdx.x >> 5);
    int lane = threadIdx.x & 31;
    if (gid >= B_ * (T_ - 1)) return;
    int b = gid / (T_ - 1), t = gid % (T_ - 1);
    int row = b * T_ + t;
    float Mv = -1e30f, Sv = 0.f;
    for (int i = lane; i < NBN_V; i += 32) {
        float mi = g_lpart[((size_t)row * NBN_V + i) * 2];
        float si = g_lpart[((size_t)row * NBN_V + i) * 2 + 1];
        if (mi > Mv) { Sv = Sv * __expf(Mv - mi) + si; Mv = mi; }
        else         { Sv += si * __expf(mi - Mv); }
    }
    #pragma unroll
    for (int o = 16; o; o >>= 1) {
        float m2 = __shfl_down_sync(0xffffffffu, Mv, o);
        float s2 = __shfl_down_sync(0xffffffffu, Sv, o);
        float mN = fmaxf(Mv, m2);
        Sv = Sv * __expf(Mv - mN) + s2 * __expf(m2 - mN);
        Mv = mN;
    }
    if (lane == 0) {
        int label = targets[row + 1];
        g_logp[gid] = logits[(size_t)row * V_ + label] - Mv - logf(Sv);
    }
}

__global__ void loss_final(float* __restrict__ out, long long pos) {
    __shared__ float red[32];
    float s = 0.f;
    for (int i = threadIdx.x; i < B_ * (T_ - 1); i += 256) s += g_logp[i];
    s = blockReduceSum(s, red);
    if (threadIdx.x == 0) out[pos] = -s / (float)(B_ * (T_ - 1));
}

// ---------------- driver ----------------------------------------------------
static inline int gemm_grid(int N) {
    return (M_ >> 8) * ((N + 127) >> 7);
}

static inline void cvt_weights(const float* src, __half* dst, long long n) {
    int n4 = (int)(n >> 2);
    cvt_f16_kernel<<<(n4 + 255) / 256, 256>>>(
        (const float4*)src, (__half2*)dst, n4);
}

extern "C" void kernel_launch(void* const* d_in, const int* in_sizes, int n_in,
                              void* d_out, int out_size) {
    const int*   idx     = (const int*)  d_in[0];
    const int*   targets = (const int*)  d_in[1];
    const float* wte     = (const float*)d_in[2];
    const float* wpe     = (const float*)d_in[3];
    const float* ln1_w   = (const float*)d_in[4];
    const float* ln1_b   = (const float*)d_in[5];
    const float* attn_w  = (const float*)d_in[6];
    const float* attn_b  = (const float*)d_in[7];
    const float* proj_w  = (const float*)d_in[8];
    const float* proj_b  = (const float*)d_in[9];
    const float* ln2_w   = (const float*)d_in[10];
    const float* ln2_b   = (const float*)d_in[11];
    const float* fc_w    = (const float*)d_in[12];
    const float* fc_b    = (const float*)d_in[13];
    const float* out_w   = (const float*)d_in[14];
    const float* out_b   = (const float*)d_in[15];
    const float* lnf_w   = (const float*)d_in[16];
    const float* lnf_b   = (const float*)d_in[17];
    float* out = (float*)d_out;

    float *x, *qkv, *lpart;
    __half *h, *y, *fc;
    __half *w_attn, *w_proj, *w_fc, *w_out, *w_wte;
    cudaGetSymbolAddress((void**)&x,   g_x);
    cudaGetSymbolAddress((void**)&h,   g_h);
    cudaGetSymbolAddress((void**)&qkv, g_qkv);
    cudaGetSymbolAddress((void**)&y,   g_y);
    cudaGetSymbolAddress((void**)&fc,  g_fc);
    cudaGetSymbolAddress((void**)&lpart, g_lpart);
    cudaGetSymbolAddress((void**)&w_attn, g_w_attn);
    cudaGetSymbolAddress((void**)&w_proj, g_w_proj);
    cudaGetSymbolAddress((void**)&w_fc,   g_w_fc);
    cudaGetSymbolAddress((void**)&w_out,  g_w_out);
    cudaGetSymbolAddress((void**)&w_wte,  g_w_wte);

    cudaFuncSetAttribute(flash_attn,
                         cudaFuncAttributeMaxDynamicSharedMemorySize, FATT_SMEM);
    cudaFuncSetAttribute(gemm_f16,
                         cudaFuncAttributeMaxDynamicSharedMemorySize, GEMM_SMEM);

    cvt_weights(attn_w, w_attn, (long long)L_ * E3_ * E_);
    cvt_weights(proj_w, w_proj, (long long)L_ * E_ * E_);
    cvt_weights(fc_w,   w_fc,   (long long)L_ * E4_ * E_);
    cvt_weights(out_w,  w_out,  (long long)L_ * E_ * E4_);
    cvt_weights(wte,    w_wte,  (long long)V_ * E_);

    embed_kernel<<<(M_ * E_) / 256, 256>>>(idx, wte, wpe);

    for (int l = 0; l < L_; l++) {
        ln_kernel<<<M_ / 8, 256>>>(x, ln1_w + (size_t)l * E_, ln1_b + (size_t)l * E_, h);
        gemm_f16<<<gemm_grid(E3_), 512, GEMM_SMEM>>>(
            h, w_attn + (size_t)l * E3_ * E_, attn_b + (size_t)l * E3_,
            nullptr, qkv, nullptr, nullptr, M_, E3_, E_, 0);
        flash_attn<<<dim3(T_ / FQ, B_ * H_), 256, FATT_SMEM>>>(qkv, y);
        gemm_f16<<<gemm_grid(E_), 512, GEMM_SMEM>>>(
            y, w_proj + (size_t)l * E_ * E_, proj_b + (size_t)l * E_,
            x, x, nullptr, nullptr, M_, E_, E_, 0);
        ln_kernel<<<M_ / 8, 256>>>(x, ln2_w + (size_t)l * E_, ln2_b + (size_t)l * E_, h);
        gemm_f16<<<gemm_grid(E4_), 512, GEMM_SMEM>>>(
            h, w_fc + (size_t)l * E4_ * E_, fc_b + (size_t)l * E4_,
            nullptr, nullptr, fc, nullptr, M_, E4_, E_, 1);
        gemm_f16<<<gemm_grid(E_), 512, GEMM_SMEM>>>(
            fc, w_out + (size_t)l * E_ * E4_, out_b + (size_t)l * E_,
            x, x, nullptr, nullptr, M_, E_, E4_, 0);
    }

    ln_kernel<<<M_ / 8, 256>>>(x, lnf_w, lnf_b, h);
    gemm_f16<<<gemm_grid(V_), 512, GEMM_SMEM>>>(
        h, w_wte, nullptr, nullptr, out, nullptr, lpart, M_, V_, E_, 0);

    loss_reduce<<<(B_ * (T_ - 1) + 7) / 8, 256>>>(out, targets);
    long long pos = (long long)M_ * V_;
    if (pos < (long long)out_size)
        loss_final<<<1, 256>>>(out, pos);
}

// round 15
// speedup vs baseline: 1.0734x; 1.0734x over previous
#include <cuda_runtime.h>
#include <cuda_fp16.h>
#include <math.h>

#define L_ 4
#define H_ 12
#define E_ 768
#define T_ 1024
#define B_ 4
#define V_ 50257
#define D_ 64
#define M_ (B_*T_)     // 4096
#define E3_ (3*E_)     // 2304
#define E4_ (4*E_)     // 3072
#define NBN_V ((V_ + 127) >> 7)   // 393

// ---------------- scratch (static device globals; no allocation) ----------
__device__ float  g_x  [(size_t)M_*E_];
__device__ __half g_h  [(size_t)M_*E_];
__device__ float  g_qkv[(size_t)M_*E3_];
__device__ __half g_y  [(size_t)M_*E_];
__device__ __half g_fc [(size_t)M_*E4_];
__device__ float  g_logp[B_*(T_-1)];
__device__ float  g_lpart[(size_t)M_*NBN_V*2];
// fp16 weight copies (converted once per launch)
__device__ __half g_w_attn[(size_t)L_*E3_*E_];
__device__ __half g_w_proj[(size_t)L_*E_*E_];
__device__ __half g_w_fc  [(size_t)L_*E4_*E_];
__device__ __half g_w_out [(size_t)L_*E_*E4_];
__device__ __half g_w_wte [(size_t)V_*E_];

// ---------------- reductions ----------------------------------------------
__device__ __forceinline__ float blockReduceSum(float v, float* red) {
    int lane = threadIdx.x & 31, wid = threadIdx.x >> 5;
    #pragma unroll
    for (int o = 16; o; o >>= 1) v += __shfl_down_sync(0xffffffffu, v, o);
    __syncthreads();
    if (lane == 0) red[wid] = v;
    __syncthreads();
    if (threadIdx.x == 0) {
        float s = 0.f;
        int nw = (blockDim.x + 31) >> 5;
        for (int i = 0; i < nw; i++) s += red[i];
        red[0] = s;
    }
    __syncthreads();
    return red[0];
}

// ---------------- mma / ldmatrix helpers ------------------------------------
#define MMA_F16(acc, a0,a1,a2,a3, b0,b1)                                    \
    asm volatile(                                                            \
        "mma.sync.aligned.m16n8k16.row.col.f32.f16.f16.f32 "                \
        "{%0,%1,%2,%3}, {%4,%5,%6,%7}, {%8,%9}, {%0,%1,%2,%3};"             \
        : "+f"((acc)[0]), "+f"((acc)[1]), "+f"((acc)[2]), "+f"((acc)[3])    \
        : "r"(a0), "r"(a1), "r"(a2), "r"(a3), "r"(b0), "r"(b1))

#define LDSM_X4(r0,r1,r2,r3, addr)                                          \
    asm volatile(                                                            \
        "ldmatrix.sync.aligned.m8n8.x4.shared.b16 {%0,%1,%2,%3}, [%4];"     \
        : "=r"(r0), "=r"(r1), "=r"(r2), "=r"(r3) : "r"(addr))

#define LDSM_X4T(r0,r1,r2,r3, addr)                                         \
    asm volatile(                                                            \
        "ldmatrix.sync.aligned.m8n8.x4.trans.shared.b16 {%0,%1,%2,%3}, [%4];" \
        : "=r"(r0), "=r"(r1), "=r"(r2), "=r"(r3) : "r"(addr))

__device__ __forceinline__ unsigned smem_u32(const void* p) {
    unsigned a;
    asm("{ .reg .u64 t; cvta.to.shared.u64 t, %1; cvt.u32.u64 %0, t; }"
        : "=r"(a) : "l"(p));
    return a;
}

// split fp32 -> hi/lo fp16 and store a float4 into swizzled [row][64] tiles
__device__ __forceinline__ void store_split4(__half* hb, __half* lb,
                                             int row, int c, float4 v) {
    int ph = row * 64 + (((c >> 3) ^ (row & 7)) << 3) + (c & 7);
    __half h0 = __float2half_rn(v.x), h1 = __float2half_rn(v.y);
    __half h2 = __float2half_rn(v.z), h3 = __float2half_rn(v.w);
    *(__half2*)(hb + ph)     = __halves2half2(h0, h1);
    *(__half2*)(hb + ph + 2) = __halves2half2(h2, h3);
    *(__half2*)(lb + ph)     = __halves2half2(
        __float2half_rn(v.x - __half2float(h0)),
        __float2half_rn(v.y - __half2float(h1)));
    *(__half2*)(lb + ph + 2) = __halves2half2(
        __float2half_rn(v.z - __half2float(h2)),
        __float2half_rn(v.w - __half2float(h3)));
}

// ---------------- weight fp16 conversion -----------------------------------
__global__ void cvt_f16_kernel(const float4* __restrict__ in,
                               __half2* __restrict__ out, int n4) {
    int i = blockIdx.x * 256 + threadIdx.x;
    if (i < n4) {
        float4 v = in[i];
        out[2 * i]     = __floats2half2_rn(v.x, v.y);
        out[2 * i + 1] = __floats2half2_rn(v.z, v.w);
    }
}

// ---------------- embedding -----------------------------------------------
__global__ void embed_kernel(const int* __restrict__ idx,
                             const float* __restrict__ wte,
                             const float* __restrict__ wpe) {
    int i = blockIdx.x * 256 + threadIdx.x;
    int bt = i / E_, e = i - bt * E_;
    int t = bt & (T_ - 1);
    g_x[i] = wte[(size_t)idx[bt] * E_ + e] + wpe[(size_t)t * E_ + e];
}

// ---------------- layernorm: warp per row, fp16 output ----------------------
__global__ __launch_bounds__(256)
void ln_kernel(const float* __restrict__ in,
               const float* __restrict__ w,
               const float* __restrict__ b,
               __half* __restrict__ out) {
    int wid = threadIdx.x >> 5, lane = threadIdx.x & 31;
    int row = blockIdx.x * 8 + wid;
    const float4* x4 = (const float4*)(in + (size_t)row * E_);
    float4 v[6];
    float s = 0.f;
    #pragma unroll
    for (int i = 0; i < 6; i++) {
        v[i] = x4[lane + i * 32];
        s += v[i].x + v[i].y + v[i].z + v[i].w;
    }
    #pragma unroll
    for (int o = 16; o; o >>= 1) s += __shfl_xor_sync(0xffffffffu, s, o);
    float m = s * (1.0f / E_);
    float var = 0.f;
    #pragma unroll
    for (int i = 0; i < 6; i++) {
        float dx = v[i].x - m, dy = v[i].y - m, dz = v[i].z - m, dw = v[i].w - m;
        var += dx * dx + dy * dy + dz * dz + dw * dw;
    }
    #pragma unroll
    for (int o = 16; o; o >>= 1) var += __shfl_xor_sync(0xffffffffu, var, o);
    float r = rsqrtf(var * (1.0f / E_) + 1e-5f);
    __half* o = out + (size_t)row * E_;
    #pragma unroll
    for (int i = 0; i < 6; i++) {
        int c = (lane + i * 32) * 4;
        float4 w4 = ((const float4*)w)[lane + i * 32];
        float4 b4 = ((const float4*)b)[lane + i * 32];
        float o0 = (v[i].x - m) * r * w4.x + b4.x;
        float o1 = (v[i].y - m) * r * w4.y + b4.y;
        float o2 = (v[i].z - m) * r * w4.z + b4.z;
        float o3 = (v[i].w - m) * r * w4.w + b4.w;
        *(__half2*)(o + c)     = __floats2half2_rn(o0, o1);
        *(__half2*)(o + c + 2) = __floats2half2_rn(o2, o3);
    }
}

// ---------------- FP16 GEMM: C = A[MxK] * B[NxK]^T --------------------------
// 128x128x64 tile, 256 threads, 8 warps (2m x 4n), 3-stage cp.async,
// XOR-swizzled smem, 16-m-row L2 groups.
#define GSTAGES 3
#define STG_H 8192
#define GEMM_SMEM (GSTAGES * 2 * STG_H * 2)

__global__ __launch_bounds__(256, 2)
void gemm_f16(const __half* __restrict__ A, const __half* __restrict__ B,
              const float* __restrict__ bias, const float* __restrict__ res,
              float* __restrict__ C, __half* __restrict__ Ch,
              float* __restrict__ lpart,
              int M, int N, int K, int gelu) {
    extern __shared__ __half hsm[];
    __half* As = hsm;
    __half* Bs = hsm + GSTAGES * STG_H;

    int nbn = (N + 127) >> 7;
    int bid = blockIdx.x;
    int bpg = 16 * nbn;                  // 16 m-rows per L2 group
    int grp = bid / bpg, rr = bid % bpg;
    int m0 = (grp * 16 + (rr & 15)) << 7;
    int n0 = (rr >> 4) << 7;

    int tid = threadIdx.x;
    int lane = tid & 31, wid = tid >> 5;
    int wm = wid >> 2, wn = wid & 3;
    int la = lane & 3, lg = lane >> 2;

    int r0 = tid >> 3, c0 = tid & 7;
    int off0 = r0 * 64 + ((c0 ^ (r0 & 7)) << 3);
    const __half* aBase = A + (size_t)(m0 + r0) * K + c0 * 8;
    const __half* bP[4]; int bok[4];
    #pragma unroll
    for (int i = 0; i < 4; i++) {
        int bn = n0 + r0 + 32 * i;
        bok[i] = (bn < N) ? 16 : 0;
        bP[i] = B + (size_t)(bok[i] ? bn : 0) * K + c0 * 8;
    }
    unsigned sAb = smem_u32(As), sBb = smem_u32(Bs);

    auto issue = [&](int st, int kb) {
        unsigned ab = sAb + (unsigned)(st * STG_H + off0) * 2u;
        unsigned bb = sBb + (unsigned)(st * STG_H + off0) * 2u;
        #pragma unroll
        for (int i = 0; i < 4; i++) {
            asm volatile("cp.async.cg.shared.global [%0], [%1], 16;"
                         :: "r"(ab + i * 4096u), "l"(aBase + (size_t)i * 32 * K + kb));
        }
        #pragma unroll
        for (int i = 0; i < 4; i++) {
            asm volatile("cp.async.cg.shared.global [%0], [%1], 16, %2;"
                         :: "r"(bb + i * 4096u), "l"(bP[i] + kb), "r"(bok[i]));
        }
    };

    int l7 = lane & 7;
    unsigned aRow[4];
    #pragma unroll
    for (int mt = 0; mt < 4; mt++)
        aRow[mt] = (unsigned)((wm * 64 + mt * 16 + l7 + ((lane >> 3) & 1) * 8) * 128);
    int aCx = lane >> 4;
    unsigned bRow[2];
    #pragma unroll
    for (int p = 0; p < 2; p++)
        bRow[p] = (unsigned)((wn * 32 + p * 16 + l7 + (lane >> 4) * 8) * 128);
    int bCx = (lane >> 3) & 1;

    float acc[4][4][4];
    #pragma unroll
    for (int i = 0; i < 4; i++)
        #pragma unroll
        for (int j = 0; j < 4; j++)
            #pragma unroll
            for (int k = 0; k < 4; k++) acc[i][j][k] = 0.f;

    int nk = K >> 6;
    issue(0, 0);  asm volatile("cp.async.commit_group;");
    issue(1, 64); asm volatile("cp.async.commit_group;");

    int cst = 0, pst = 2;
    for (int kt = 0; kt < nk; kt++) {
        asm volatile("cp.async.wait_group 1;");
        __syncthreads();
        int pf = kt + 2;
        if (pf < nk) issue(pst, pf << 6);
        asm volatile("cp.async.commit_group;");
        if (++pst == GSTAGES) pst = 0;

        unsigned aS = sAb + (unsigned)(cst * STG_H) * 2u;
        unsigned bS = sBb + (unsigned)(cst * STG_H) * 2u;
        if (++cst == GSTAGES) cst = 0;

        #pragma unroll
        for (int ks = 0; ks < 4; ks++) {
            unsigned af[4][4], bf[4][2];
            #pragma unroll
            for (int mt = 0; mt < 4; mt++) {
                unsigned ad = aS + aRow[mt] + (unsigned)((((2 * ks + aCx) ^ l7)) << 4);
                LDSM_X4(af[mt][0], af[mt][1], af[mt][2], af[mt][3], ad);
            }
            #pragma unroll
            for (int p = 0; p < 2; p++) {
                unsigned bd = bS + bRow[p] + (unsigned)((((2 * ks + bCx) ^ l7)) << 4);
                LDSM_X4(bf[2*p][0], bf[2*p][1], bf[2*p+1][0], bf[2*p+1][1], bd);
            }
            #pragma unroll
            for (int mt = 0; mt < 4; mt++)
                #pragma unroll
                for (int nt = 0; nt < 4; nt++)
                    MMA_F16(acc[mt][nt], af[mt][0], af[mt][1], af[mt][2], af[mt][3],
                            bf[nt][0], bf[nt][1]);
        }
    }

    if (bias) {
        #pragma unroll
        for (int nt = 0; nt < 4; nt++) {
            int cb = n0 + wn * 32 + nt * 8 + la * 2;
            float b0 = (cb < N)     ? bias[cb]     : 0.f;
            float b1 = (cb + 1 < N) ? bias[cb + 1] : 0.f;
            #pragma unroll
            for (int mt = 0; mt < 4; mt++) {
                acc[mt][nt][0] += b0; acc[mt][nt][1] += b1;
                acc[mt][nt][2] += b0; acc[mt][nt][3] += b1;
            }
        }
    }

    #pragma unroll
    for (int mt = 0; mt < 4; mt++) {
        int rbase = m0 + wm * 64 + mt * 16 + lg;
        #pragma unroll
        for (int nt = 0; nt < 4; nt++) {
            int cbase = n0 + wn * 32 + nt * 8 + la * 2;
            #pragma unroll
            for (int hf = 0; hf < 2; hf++) {
                int rw = rbase + hf * 8;
                #pragma unroll
                for (int cc = 0; cc < 2; cc++) {
                    int c = cbase + cc;
                    if (c < N) {
                        float v = acc[mt][nt][hf * 2 + cc];
                        if (gelu) {
                            float u = v;
                            float w = 0.7978845608028654f * (u + 0.044715f * u * u * u);
                            v = u / (1.0f + __expf(-2.0f * w));
                        }
                        size_t off = (size_t)rw * N + c;
                        if (Ch) {
                            Ch[off] = __float2half_rn(v);
                        } else {
                            if (res) v += res[off];
                            C[off] = v;
                        }
                    }
                }
            }
        }
    }

    if (lpart) {
        asm volatile("cp.async.wait_group 0;");
        __syncthreads();
        float* red = (float*)hsm;
        #pragma unroll
        for (int mt = 0; mt < 4; mt++) {
            #pragma unroll
            for (int hf = 0; hf < 2; hf++) {
                int wrow = wm * 64 + mt * 16 + lg + hf * 8;
                float vmax = -1e30f;
                #pragma unroll
                for (int nt = 0; nt < 4; nt++)
                    #pragma unroll
                    for (int cc = 0; cc < 2; cc++) {
                        int c = n0 + wn * 32 + nt * 8 + la * 2 + cc;
                        if (c < N) vmax = fmaxf(vmax, acc[mt][nt][hf * 2 + cc]);
                    }
                vmax = fmaxf(vmax, __shfl_xor_sync(0xffffffffu, vmax, 1));
                vmax = fmaxf(vmax, __shfl_xor_sync(0xffffffffu, vmax, 2));
                float vsum = 0.f;
                #pragma unroll
                for (int nt = 0; nt < 4; nt++)
                    #pragma unroll
                    for (int cc = 0; cc < 2; cc++) {
                        int c = n0 + wn * 32 + nt * 8 + la * 2 + cc;
                        if (c < N) vsum += __expf(acc[mt][nt][hf * 2 + cc] - vmax);
                    }
                vsum += __shfl_xor_sync(0xffffffffu, vsum, 1);
                vsum += __shfl_xor_sync(0xffffffffu, vsum, 2);
                if (la == 0) {
                    red[(wrow * 4 + wn) * 2]     = vmax;
                    red[(wrow * 4 + wn) * 2 + 1] = vsum;
                }
            }
        }
        __syncthreads();
        if (tid < 128) {
            float Mv = -1e30f, Sv = 0.f;
            #pragma unroll
            for (int w = 0; w < 4; w++) {
                float mi = red[(tid * 4 + w) * 2];
                float si = red[(tid * 4 + w) * 2 + 1];
                if (mi > Mv) { Sv = Sv * __expf(Mv - mi) + si; Mv = mi; }
                else         { Sv += si * __expf(mi - Mv); }
            }
            size_t pidx = ((size_t)(m0 + tid) * nbn + (n0 >> 7)) * 2;
            lpart[pidx]     = Mv;
            lpart[pidx + 1] = Sv;
        }
    }
}

// ---------------- flash attention v2 (R11 exact) ----------------------------
#define FQ 128
#define FATT_SMEM (49152 * 2)

__global__ __launch_bounds__(256)
void flash_attn(const float* __restrict__ qkv, __half* __restrict__ y) {
    extern __shared__ __half fh[];
    __half *Qh = fh,          *Ql = fh + 8192;
    __half *Kh = fh + 16384,  *Kl = fh + 20480;
    __half *Vh = fh + 24576,  *Vl = fh + 28672;
    __half *Ph = fh + 32768,  *Pl = fh + 40960;

    int bh = blockIdx.y;
    int b = bh / H_, h = bh % H_;
    int q0 = blockIdx.x * FQ;
    int tid = threadIdx.x;
    int lane = tid & 31, wid = tid >> 5;
    int la = lane & 3, lg = lane >> 2;
    int l7 = lane & 7;

    unsigned sb = smem_u32(fh);
    unsigned sQh = sb, sQl = sb + 16384;
    unsigned sKh = sb + 32768, sKl = sb + 40960;
    unsigned sVh = sb + 49152, sVl = sb + 57344;
    unsigned sPh = sb + 65536, sPl = sb + 81920;

    #pragma unroll
    for (int i = 0; i < 8; i++) {
        int f4 = tid + i * 256;
        int row = f4 >> 4, c = (f4 & 15) << 2;
        float4 v = *(const float4*)(qkv + (size_t)(b * T_ + q0 + row) * E3_ + h * D_ + c);
        store_split4(Qh, Ql, row, c, v);
    }
    __syncthreads();

    int aCx = lane >> 4;
    unsigned qRowOff = (unsigned)((wid * 16 + l7 + ((lane >> 3) & 1) * 8) * 128);
    unsigned qfh[4][4], qfl[4][4];
    #pragma unroll
    for (int kc = 0; kc < 4; kc++) {
        unsigned cx = (unsigned)((((2 * kc + aCx) ^ l7)) << 4);
        LDSM_X4(qfh[kc][0], qfh[kc][1], qfh[kc][2], qfh[kc][3], sQh + qRowOff + cx);
        LDSM_X4(qfl[kc][0], qfl[kc][1], qfl[kc][2], qfl[kc][3], sQl + qRowOff + cx);
    }

    float m0r = -1e30f, m1r = -1e30f, l0r = 0.f, l1r = 0.f;
    float acc_o[8][4];
    #pragma unroll
    for (int i = 0; i < 8; i++)
        #pragma unroll
        for (int j = 0; j < 4; j++) acc_o[i][j] = 0.f;

    int row0g = q0 + wid * 16 + lg;
    int row1g = row0g + 8;
    int lastNeeded = (q0 + wid * 16 + 15) >> 6;
    int nkt = (q0 >> 6) + 2;

    for (int kt = 0; kt < nkt; kt++) {
        int k0 = kt << 6;
        __syncthreads();
        #pragma unroll
        for (int i = 0; i < 4; i++) {
            int f4 = tid + i * 256;
            int row = f4 >> 4, c = (f4 & 15) << 2;
            const float* base = qkv + (size_t)(b * T_ + k0 + row) * E3_ + h * D_ + c;
            float4 kv = *(const float4*)(base + E_);
            float4 vv = *(const float4*)(base + 2 * E_);
            store_split4(Kh, Kl, row, c, kv);
            store_split4(Vh, Vl, row, c, vv);
        }
        __syncthreads();
        if (kt > lastNeeded) continue;

        float s[8][4];
        #pragma unroll
        for (int i = 0; i < 8; i++)
            #pragma unroll
            for (int j = 0; j < 4; j++) s[i][j] = 0.f;

        int bCx = (lane >> 3) & 1;
        #pragma unroll
        for (int kc = 0; kc < 4; kc++) {
            unsigned kfh[8][2], kfl[8][2];
            #pragma unroll
            for (int p = 0; p < 4; p++) {
                unsigned rOff = (unsigned)((p * 16 + l7 + ((lane >> 4) << 3)) * 128);
                unsigned cx = (unsigned)((((2 * kc + bCx) ^ l7)) << 4);
                LDSM_X4(kfh[2*p][0], kfh[2*p][1], kfh[2*p+1][0], kfh[2*p+1][1],
                        sKh + rOff + cx);
                LDSM_X4(kfl[2*p][0], kfl[2*p][1], kfl[2*p+1][0], kfl[2*p+1][1],
                        sKl + rOff + cx);
            }
            #pragma unroll
            for (int nt = 0; nt < 8; nt++) {
                MMA_F16(s[nt], qfl[kc][0], qfl[kc][1], qfl[kc][2], qfl[kc][3],
                        kfh[nt][0], kfh[nt][1]);
                MMA_F16(s[nt], qfh[kc][0], qfh[kc][1], qfh[kc][2], qfh[kc][3],
                        kfl[nt][0], kfl[nt][1]);
                MMA_F16(s[nt], qfh[kc][0], qfh[kc][1], qfh[kc][2], qfh[kc][3],
                        kfh[nt][0], kfh[nt][1]);
            }
        }

        #pragma unroll
        for (int nt = 0; nt < 8; nt++) {
            int c0c = k0 + nt * 8 + 2 * la;
            s[nt][0] = (c0c     <= row0g) ? s[nt][0] * 0.125f : -1e30f;
            s[nt][1] = (c0c + 1 <= row0g) ? s[nt][1] * 0.125f : -1e30f;
            s[nt][2] = (c0c     <= row1g) ? s[nt][2] * 0.125f : -1e30f;
            s[nt][3] = (c0c + 1 <= row1g) ? s[nt][3] * 0.125f : -1e30f;
        }

        float mx0 = -1e30f, mx1 = -1e30f;
        #pragma unroll
        for (int nt = 0; nt < 8; nt++) {
            mx0 = fmaxf(mx0, fmaxf(s[nt][0], s[nt][1]));
            mx1 = fmaxf(mx1, fmaxf(s[nt][2], s[nt][3]));
        }
        mx0 = fmaxf(mx0, __shfl_xor_sync(0xffffffffu, mx0, 1));
        mx0 = fmaxf(mx0, __shfl_xor_sync(0xffffffffu, mx0, 2));
        mx1 = fmaxf(mx1, __shfl_xor_sync(0xffffffffu, mx1, 1));
        mx1 = fmaxf(mx1, __shfl_xor_sync(0xffffffffu, mx1, 2));
        float m0n = fmaxf(m0r, mx0), m1n = fmaxf(m1r, mx1);
        float a0 = __expf(m0r - m0n), a1 = __expf(m1r - m1n);
        m0r = m0n; m1r = m1n;

        float ts0 = 0.f, ts1 = 0.f;
        #pragma unroll
        for (int nt = 0; nt < 8; nt++) {
            s[nt][0] = __expf(s[nt][0] - m0n);
            s[nt][1] = __expf(s[nt][1] - m0n);
            s[nt][2] = __expf(s[nt][2] - m1n);
            s[nt][3] = __expf(s[nt][3] - m1n);
            ts0 += s[nt][0] + s[nt][1];
            ts1 += s[nt][2] + s[nt][3];
        }
        ts0 += __shfl_xor_sync(0xffffffffu, ts0, 1);
        ts0 += __shfl_xor_sync(0xffffffffu, ts0, 2);
        ts1 += __shfl_xor_sync(0xffffffffu, ts1, 1);
        ts1 += __shfl_xor_sync(0xffffffffu, ts1, 2);
        l0r = l0r * a0 + ts0;
        l1r = l1r * a1 + ts1;
        #pragma unroll
        for (int nt = 0; nt < 8; nt++) {
            acc_o[nt][0] *= a0; acc_o[nt][1] *= a0;
            acc_o[nt][2] *= a1; acc_o[nt][3] *= a1;
        }

        __half* Pwh = Ph + wid * 1024;
        __half* Pwl = Pl + wid * 1024;
        #pragma unroll
        for (int nt = 0; nt < 8; nt++) {
            int ph0 = lg * 64 + ((nt ^ (lg & 7)) << 3) + 2 * la;
            __half h0 = __float2half_rn(s[nt][0]), h1 = __float2half_rn(s[nt][1]);
            *(__half2*)(Pwh + ph0) = __halves2half2(h0, h1);
            *(__half2*)(Pwl + ph0) = __halves2half2(
                __float2half_rn(s[nt][0] - __half2float(h0)),
                __float2half_rn(s[nt][1] - __half2float(h1)));
            int ph1 = ph0 + 8 * 64;
            __half h2 = __float2half_rn(s[nt][2]), h3 = __float2half_rn(s[nt][3]);
            *(__half2*)(Pwh + ph1) = __halves2half2(h2, h3);
            *(__half2*)(Pwl + ph1) = __halves2half2(
                __float2half_rn(s[nt][2] - __half2float(h2)),
                __float2half_rn(s[nt][3] - __half2float(h3)));
        }
        __syncwarp();

        unsigned pRowOff = (unsigned)((l7 + ((lane >> 3) & 1) * 8) * 128)
                         + (unsigned)(wid * 2048);
        #pragma unroll
        for (int kc = 0; kc < 4; kc++) {
            unsigned pfh[4], pfl[4];
            unsigned cx = (unsigned)((((2 * kc + aCx) ^ l7)) << 4);
            LDSM_X4(pfh[0], pfh[1], pfh[2], pfh[3], sPh + pRowOff + cx);
            LDSM_X4(pfl[0], pfl[1], pfl[2], pfl[3], sPl + pRowOff + cx);
            unsigned vfh[8][2], vfl[8][2];
            int vrow = kc * 16 + l7 + ((lane >> 3) & 1) * 8;
            #pragma unroll
            for (int pd = 0; pd < 4; pd++) {
                int dgc = 2 * pd + (lane >> 4);
                unsigned voff = (unsigned)(vrow * 128 + (((dgc) ^ (vrow & 7)) << 4));
                LDSM_X4T(vfh[2*pd][0], vfh[2*pd][1], vfh[2*pd+1][0], vfh[2*pd+1][1],
                         sVh + voff);
                LDSM_X4T(vfl[2*pd][0], vfl[2*pd][1], vfl[2*pd+1][0], vfl[2*pd+1][1],
                         sVl + voff);
            }
            #pragma unroll
            for (int nt = 0; nt < 8; nt++) {
                MMA_F16(acc_o[nt], pfl[0], pfl[1], pfl[2], pfl[3],
                        vfh[nt][0], vfh[nt][1]);
                MMA_F16(acc_o[nt], pfh[0], pfh[1], pfh[2], pfh[3],
                        vfl[nt][0], vfl[nt][1]);
                MMA_F16(acc_o[nt], pfh[0], pfh[1], pfh[2], pfh[3],
                        vfh[nt][0], vfh[nt][1]);
            }
        }
    }

    float inv0 = 1.0f / l0r, inv1 = 1.0f / l1r;
    size_t o0 = (size_t)(b * T_ + q0 + wid * 16 + lg) * E_ + h * D_;
    size_t o1 = o0 + 8 * E_;
    #pragma unroll
    for (int nt = 0; nt < 8; nt++) {
        int c = nt * 8 + 2 * la;
        *(__half2*)(y + o0 + c) = __floats2half2_rn(acc_o[nt][0] * inv0,
                                                    acc_o[nt][1] * inv0);
        *(__half2*)(y + o1 + c) = __floats2half2_rn(acc_o[nt][2] * inv1,
                                                    acc_o[nt][3] * inv1);
    }
}

// ---------------- loss: combine per-block partials (one warp per row) -------
__global__ __launch_bounds__(256)
void loss_reduce(const float* __restrict__ logits,
                 const int* __restrict__ targets) {
    int gid = blockIdx.x * 8 + (threadIdx.x >> 5);
    int lane = threadIdx.x & 31;
    if (gid >= B_ * (T_ - 1)) return;
    int b = gid / (T_ - 1), t = gid % (T_ - 1);
    int row = b * T_ + t;
    float Mv = -1e30f, Sv = 0.f;
    for (int i = lane; i < NBN_V; i += 32) {
        float mi = g_lpart[((size_t)row * NBN_V + i) * 2];
        float si = g_lpart[((size_t)row * NBN_V + i) * 2 + 1];
        if (mi > Mv) { Sv = Sv * __expf(Mv - mi) + si; Mv = mi; }
        else         { Sv += si * __expf(mi - Mv); }
    }
    #pragma unroll
    for (int o = 16; o; o >>= 1) {
        float m2 = __shfl_down_sync(0xffffffffu, Mv, o);
        float s2 = __shfl_down_sync(0xffffffffu, Sv, o);
        float mN = fmaxf(Mv, m2);
        Sv = Sv * __expf(Mv - mN) + s2 * __expf(m2 - mN);
        Mv = mN;
    }
    if (lane == 0) {
        int label = targets[row + 1];
        g_logp[gid] = logits[(size_t)row * V_ + label] - Mv - logf(Sv);
    }
}

__global__ void loss_final(float* __restrict__ out, long long pos) {
    __shared__ float red[32];
    float s = 0.f;
    for (int i = threadIdx.x; i < B_ * (T_ - 1); i += 256) s += g_logp[i];
    s = blockReduceSum(s, red);
    if (threadIdx.x == 0) out[pos] = -s / (float)(B_ * (T_ - 1));
}

// ---------------- driver ----------------------------------------------------
static inline int gemm_grid(int N) {
    return (M_ >> 7) * ((N + 127) >> 7);
}

static inline void cvt_weights(const float* src, __half* dst, long long n) {
    int n4 = (int)(n >> 2);
    cvt_f16_kernel<<<(n4 + 255) / 256, 256>>>(
        (const float4*)src, (__half2*)dst, n4);
}

extern "C" void kernel_launch(void* const* d_in, const int* in_sizes, int n_in,
                              void* d_out, int out_size) {
    const int*   idx     = (const int*)  d_in[0];
    const int*   targets = (const int*)  d_in[1];
    const float* wte     = (const float*)d_in[2];
    const float* wpe     = (const float*)d_in[3];
    const float* ln1_w   = (const float*)d_in[4];
    const float* ln1_b   = (const float*)d_in[5];
    const float* attn_w  = (const float*)d_in[6];
    const float* attn_b  = (const float*)d_in[7];
    const float* proj_w  = (const float*)d_in[8];
    const float* proj_b  = (const float*)d_in[9];
    const float* ln2_w   = (const float*)d_in[10];
    const float* ln2_b   = (const float*)d_in[11];
    const float* fc_w    = (const float*)d_in[12];
    const float* fc_b    = (const float*)d_in[13];
    const float* out_w   = (const float*)d_in[14];
    const float* out_b   = (const float*)d_in[15];
    const float* lnf_w   = (const float*)d_in[16];
    const float* lnf_b   = (const float*)d_in[17];
    float* out = (float*)d_out;

    float *x, *qkv, *lpart;
    __half *h, *y, *fc;
    __half *w_attn, *w_proj, *w_fc, *w_out, *w_wte;
    cudaGetSymbolAddress((void**)&x,   g_x);
    cudaGetSymbolAddress((void**)&h,   g_h);
    cudaGetSymbolAddress((void**)&qkv, g_qkv);
    cudaGetSymbolAddress((void**)&y,   g_y);
    cudaGetSymbolAddress((void**)&fc,  g_fc);
    cudaGetSymbolAddress((void**)&lpart, g_lpart);
    cudaGetSymbolAddress((void**)&w_attn, g_w_attn);
    cudaGetSymbolAddress((void**)&w_proj, g_w_proj);
    cudaGetSymbolAddress((void**)&w_fc,   g_w_fc);
    cudaGetSymbolAddress((void**)&w_out,  g_w_out);
    cudaGetSymbolAddress((void**)&w_wte,  g_w_wte);

    cudaFuncSetAttribute(flash_attn,
                         cudaFuncAttributeMaxDynamicSharedMemorySize, FATT_SMEM);
    cudaFuncSetAttribute(gemm_f16,
                         cudaFuncAttributeMaxDynamicSharedMemorySize, GEMM_SMEM);

    cvt_weights(attn_w, w_attn, (long long)L_ * E3_ * E_);
    cvt_weights(proj_w, w_proj, (long long)L_ * E_ * E_);
    cvt_weights(fc_w,   w_fc,   (long long)L_ * E4_ * E_);
    cvt_weights(out_w,  w_out,  (long long)L_ * E_ * E4_);
    cvt_weights(wte,    w_wte,  (long long)V_ * E_);

    embed_kernel<<<(M_ * E_) / 256, 256>>>(idx, wte, wpe);

    for (int l = 0; l < L_; l++) {
        ln_kernel<<<M_ / 8, 256>>>(x, ln1_w + (size_t)l * E_, ln1_b + (size_t)l * E_, h);
        gemm_f16<<<gemm_grid(E3_), 256, GEMM_SMEM>>>(
            h, w_attn + (size_t)l * E3_ * E_, attn_b + (size_t)l * E3_,
            nullptr, qkv, nullptr, nullptr, M_, E3_, E_, 0);
        flash_attn<<<dim3(T_ / FQ, B_ * H_), 256, FATT_SMEM>>>(qkv, y);
        gemm_f16<<<gemm_grid(E_), 256, GEMM_SMEM>>>(
            y, w_proj + (size_t)l * E_ * E_, proj_b + (size_t)l * E_,
            x, x, nullptr, nullptr, M_, E_, E_, 0);
        ln_kernel<<<M_ / 8, 256>>>(x, ln2_w + (size_t)l * E_, ln2_b + (size_t)l * E_, h);
        gemm_f16<<<gemm_grid(E4_), 256, GEMM_SMEM>>>(
            h, w_fc + (size_t)l * E4_ * E_, fc_b + (size_t)l * E4_,
            nullptr, nullptr, fc, nullptr, M_, E4_, E_, 1);
        gemm_f16<<<gemm_grid(E_), 256, GEMM_SMEM>>>(
            fc, w_out + (size_t)l * E_ * E4_, out_b + (size_t)l * E_,
            x, x, nullptr, nullptr, M_, E_, E4_, 0);
    }

    ln_kernel<<<M_ / 8, 256>>>(x, lnf_w, lnf_b, h);
    gemm_f16<<<gemm_grid(V_), 256, GEMM_SMEM>>>(
        h, w_wte, nullptr, nullptr, out, nullptr, lpart, M_, V_, E_, 0);

    loss_reduce<<<(B_ * (T_ - 1) + 7) / 8, 256>>>(out, targets);
    long long pos = (long long)M_ * V_;
    if (pos < (long long)out_size)
        loss_final<<<1, 256>>>(out, pos);
}

// round 16
// speedup vs baseline: 1.1030x; 1.0276x over previous
#include <cuda_runtime.h>
#include <cuda_fp16.h>
#include <math.h>

#define L_ 4
#define H_ 12
#define E_ 768
#define T_ 1024
#define B_ 4
#define V_ 50257
#define D_ 64
#define M_ (B_*T_)     // 4096
#define E3_ (3*E_)     // 2304
#define E4_ (4*E_)     // 3072
#define NBN_V ((V_ + 127) >> 7)   // 393

// ---------------- scratch (static device globals; no allocation) ----------
__device__ float  g_x  [(size_t)M_*E_];
__device__ __half g_h  [(size_t)M_*E_];
__device__ __half g_qh [(size_t)M_*E3_];       // qkv hi (fp16)
__device__ __half g_ql [(size_t)M_*E3_];       // qkv lo (fp16 residual)
__device__ __half g_y  [(size_t)M_*E_];
__device__ __half g_fc [(size_t)M_*E4_];
__device__ float  g_logp[B_*(T_-1)];
__device__ float  g_lpart[(size_t)M_*NBN_V*2];
// fp16 weight copies (converted once per launch)
__device__ __half g_w_attn[(size_t)L_*E3_*E_];
__device__ __half g_w_proj[(size_t)L_*E_*E_];
__device__ __half g_w_fc  [(size_t)L_*E4_*E_];
__device__ __half g_w_out [(size_t)L_*E_*E4_];
__device__ __half g_w_wte [(size_t)V_*E_];

// ---------------- reductions ----------------------------------------------
__device__ __forceinline__ float blockReduceSum(float v, float* red) {
    int lane = threadIdx.x & 31, wid = threadIdx.x >> 5;
    #pragma unroll
    for (int o = 16; o; o >>= 1) v += __shfl_down_sync(0xffffffffu, v, o);
    __syncthreads();
    if (lane == 0) red[wid] = v;
    __syncthreads();
    if (threadIdx.x == 0) {
        float s = 0.f;
        int nw = (blockDim.x + 31) >> 5;
        for (int i = 0; i < nw; i++) s += red[i];
        red[0] = s;
    }
    __syncthreads();
    return red[0];
}

// ---------------- mma / ldmatrix helpers ------------------------------------
#define MMA_F16(acc, a0,a1,a2,a3, b0,b1)                                    \
    asm volatile(                                                            \
        "mma.sync.aligned.m16n8k16.row.col.f32.f16.f16.f32 "                \
        "{%0,%1,%2,%3}, {%4,%5,%6,%7}, {%8,%9}, {%0,%1,%2,%3};"             \
        : "+f"((acc)[0]), "+f"((acc)[1]), "+f"((acc)[2]), "+f"((acc)[3])    \
        : "r"(a0), "r"(a1), "r"(a2), "r"(a3), "r"(b0), "r"(b1))

#define LDSM_X4(r0,r1,r2,r3, addr)                                          \
    asm volatile(                                                            \
        "ldmatrix.sync.aligned.m8n8.x4.shared.b16 {%0,%1,%2,%3}, [%4];"     \
        : "=r"(r0), "=r"(r1), "=r"(r2), "=r"(r3) : "r"(addr))

#define LDSM_X4T(r0,r1,r2,r3, addr)                                         \
    asm volatile(                                                            \
        "ldmatrix.sync.aligned.m8n8.x4.trans.shared.b16 {%0,%1,%2,%3}, [%4];" \
        : "=r"(r0), "=r"(r1), "=r"(r2), "=r"(r3) : "r"(addr))

#define CP16(dst, src)                                                      \
    asm volatile("cp.async.cg.shared.global [%0], [%1], 16;"                \
                 :: "r"(dst), "l"(src))

__device__ __forceinline__ unsigned smem_u32(const void* p) {
    unsigned a;
    asm("{ .reg .u64 t; cvta.to.shared.u64 t, %1; cvt.u32.u64 %0, t; }"
        : "=r"(a) : "l"(p));
    return a;
}

// ---------------- weight fp16 conversion -----------------------------------
__global__ void cvt_f16_kernel(const float4* __restrict__ in,
                               __half2* __restrict__ out, int n4) {
    int i = blockIdx.x * 256 + threadIdx.x;
    if (i < n4) {
        float4 v = in[i];
        out[2 * i]     = __floats2half2_rn(v.x, v.y);
        out[2 * i + 1] = __floats2half2_rn(v.z, v.w);
    }
}

// ---------------- embedding -----------------------------------------------
__global__ void embed_kernel(const int* __restrict__ idx,
                             const float* __restrict__ wte,
                             const float* __restrict__ wpe) {
    int i = blockIdx.x * 256 + threadIdx.x;
    int bt = i / E_, e = i - bt * E_;
    int t = bt & (T_ - 1);
    g_x[i] = wte[(size_t)idx[bt] * E_ + e] + wpe[(size_t)t * E_ + e];
}

// ---------------- layernorm: warp per row, fp16 output ----------------------
__global__ __launch_bounds__(256)
void ln_kernel(const float* __restrict__ in,
               const float* __restrict__ w,
               const float* __restrict__ b,
               __half* __restrict__ out) {
    int wid = threadIdx.x >> 5, lane = threadIdx.x & 31;
    int row = blockIdx.x * 8 + wid;
    const float4* x4 = (const float4*)(in + (size_t)row * E_);
    float4 v[6];
    float s = 0.f;
    #pragma unroll
    for (int i = 0; i < 6; i++) {
        v[i] = x4[lane + i * 32];
        s += v[i].x + v[i].y + v[i].z + v[i].w;
    }
    #pragma unroll
    for (int o = 16; o; o >>= 1) s += __shfl_xor_sync(0xffffffffu, s, o);
    float m = s * (1.0f / E_);
    float var = 0.f;
    #pragma unroll
    for (int i = 0; i < 6; i++) {
        float dx = v[i].x - m, dy = v[i].y - m, dz = v[i].z - m, dw = v[i].w - m;
        var += dx * dx + dy * dy + dz * dz + dw * dw;
    }
    #pragma unroll
    for (int o = 16; o; o >>= 1) var += __shfl_xor_sync(0xffffffffu, var, o);
    float r = rsqrtf(var * (1.0f / E_) + 1e-5f);
    __half* o = out + (size_t)row * E_;
    #pragma unroll
    for (int i = 0; i < 6; i++) {
        int c = (lane + i * 32) * 4;
        float4 w4 = ((const float4*)w)[lane + i * 32];
        float4 b4 = ((const float4*)b)[lane + i * 32];
        float o0 = (v[i].x - m) * r * w4.x + b4.x;
        float o1 = (v[i].y - m) * r * w4.y + b4.y;
        float o2 = (v[i].z - m) * r * w4.z + b4.z;
        float o3 = (v[i].w - m) * r * w4.w + b4.w;
        *(__half2*)(o + c)     = __floats2half2_rn(o0, o1);
        *(__half2*)(o + c + 2) = __floats2half2_rn(o2, o3);
    }
}

// ---------------- FP16 GEMM: C = A[MxK] * B[NxK]^T --------------------------
// 128x128x64 tile, 256 threads, 8 warps (2m x 4n), 3-stage cp.async,
// XOR-swizzled smem, 16-m-row L2 groups.
// Output paths: fp32 C (+res, float2 when N even), fp16 Ch (half2-packed),
// or hi/lo pair (Ch, Cl) half2-packed. Optional fused loss partials.
#define GSTAGES 3
#define STG_H 8192
#define GEMM_SMEM (GSTAGES * 2 * STG_H * 2)

__global__ __launch_bounds__(256, 2)
void gemm_f16(const __half* __restrict__ A, const __half* __restrict__ B,
              const float* __restrict__ bias, const float* __restrict__ res,
              float* __restrict__ C, __half* __restrict__ Ch,
              __half* __restrict__ Cl, float* __restrict__ lpart,
              int M, int N, int K, int gelu) {
    extern __shared__ __half hsm[];
    __half* As = hsm;
    __half* Bs = hsm + GSTAGES * STG_H;

    int nbn = (N + 127) >> 7;
    int bid = blockIdx.x;
    int bpg = 16 * nbn;                  // 16 m-rows per L2 group
    int grp = bid / bpg, rr = bid % bpg;
    int m0 = (grp * 16 + (rr & 15)) << 7;
    int n0 = (rr >> 4) << 7;

    int tid = threadIdx.x;
    int lane = tid & 31, wid = tid >> 5;
    int wm = wid >> 2, wn = wid & 3;
    int la = lane & 3, lg = lane >> 2;

    int r0 = tid >> 3, c0 = tid & 7;
    int off0 = r0 * 64 + ((c0 ^ (r0 & 7)) << 3);
    const __half* aBase = A + (size_t)(m0 + r0) * K + c0 * 8;
    const __half* bP[4]; int bok[4];
    #pragma unroll
    for (int i = 0; i < 4; i++) {
        int bn = n0 + r0 + 32 * i;
        bok[i] = (bn < N) ? 16 : 0;
        bP[i] = B + (size_t)(bok[i] ? bn : 0) * K + c0 * 8;
    }
    unsigned sAb = smem_u32(As), sBb = smem_u32(Bs);

    auto issue = [&](int st, int kb) {
        unsigned ab = sAb + (unsigned)(st * STG_H + off0) * 2u;
        unsigned bb = sBb + (unsigned)(st * STG_H + off0) * 2u;
        #pragma unroll
        for (int i = 0; i < 4; i++) {
            asm volatile("cp.async.cg.shared.global [%0], [%1], 16;"
                         :: "r"(ab + i * 4096u), "l"(aBase + (size_t)i * 32 * K + kb));
        }
        #pragma unroll
        for (int i = 0; i < 4; i++) {
            asm volatile("cp.async.cg.shared.global [%0], [%1], 16, %2;"
                         :: "r"(bb + i * 4096u), "l"(bP[i] + kb), "r"(bok[i]));
        }
    };

    int l7 = lane & 7;
    unsigned aRow[4];
    #pragma unroll
    for (int mt = 0; mt < 4; mt++)
        aRow[mt] = (unsigned)((wm * 64 + mt * 16 + l7 + ((lane >> 3) & 1) * 8) * 128);
    int aCx = lane >> 4;
    unsigned bRow[2];
    #pragma unroll
    for (int p = 0; p < 2; p++)
        bRow[p] = (unsigned)((wn * 32 + p * 16 + l7 + (lane >> 4) * 8) * 128);
    int bCx = (lane >> 3) & 1;

    float acc[4][4][4];
    #pragma unroll
    for (int i = 0; i < 4; i++)
        #pragma unroll
        for (int j = 0; j < 4; j++)
            #pragma unroll
            for (int k = 0; k < 4; k++) acc[i][j][k] = 0.f;

    int nk = K >> 6;
    issue(0, 0);  asm volatile("cp.async.commit_group;");
    issue(1, 64); asm volatile("cp.async.commit_group;");

    int cst = 0, pst = 2;
    for (int kt = 0; kt < nk; kt++) {
        asm volatile("cp.async.wait_group 1;");
        __syncthreads();
        int pf = kt + 2;
        if (pf < nk) issue(pst, pf << 6);
        asm volatile("cp.async.commit_group;");
        if (++pst == GSTAGES) pst = 0;

        unsigned aS = sAb + (unsigned)(cst * STG_H) * 2u;
        unsigned bS = sBb + (unsigned)(cst * STG_H) * 2u;
        if (++cst == GSTAGES) cst = 0;

        #pragma unroll
        for (int ks = 0; ks < 4; ks++) {
            unsigned af[4][4], bf[4][2];
            #pragma unroll
            for (int mt = 0; mt < 4; mt++) {
                unsigned ad = aS + aRow[mt] + (unsigned)((((2 * ks + aCx) ^ l7)) << 4);
                LDSM_X4(af[mt][0], af[mt][1], af[mt][2], af[mt][3], ad);
            }
            #pragma unroll
            for (int p = 0; p < 2; p++) {
                unsigned bd = bS + bRow[p] + (unsigned)((((2 * ks + bCx) ^ l7)) << 4);
                LDSM_X4(bf[2*p][0], bf[2*p][1], bf[2*p+1][0], bf[2*p+1][1], bd);
            }
            #pragma unroll
            for (int mt = 0; mt < 4; mt++)
                #pragma unroll
                for (int nt = 0; nt < 4; nt++)
                    MMA_F16(acc[mt][nt], af[mt][0], af[mt][1], af[mt][2], af[mt][3],
                            bf[nt][0], bf[nt][1]);
        }
    }

    if (bias) {
        #pragma unroll
        for (int nt = 0; nt < 4; nt++) {
            int cb = n0 + wn * 32 + nt * 8 + la * 2;
            float b0 = (cb < N)     ? bias[cb]     : 0.f;
            float b1 = (cb + 1 < N) ? bias[cb + 1] : 0.f;
            #pragma unroll
            for (int mt = 0; mt < 4; mt++) {
                acc[mt][nt][0] += b0; acc[mt][nt][1] += b1;
                acc[mt][nt][2] += b0; acc[mt][nt][3] += b1;
            }
        }
    }

    // epilogue
    bool evenN = ((N & 1) == 0);
    #pragma unroll
    for (int mt = 0; mt < 4; mt++) {
        int rbase = m0 + wm * 64 + mt * 16 + lg;
        #pragma unroll
        for (int nt = 0; nt < 4; nt++) {
            int cbase = n0 + wn * 32 + nt * 8 + la * 2;
            #pragma unroll
            for (int hf = 0; hf < 2; hf++) {
                int rw = rbase + hf * 8;
                float v0 = acc[mt][nt][hf * 2];
                float v1 = acc[mt][nt][hf * 2 + 1];
                if (gelu) {
                    float u = v0;
                    float w = 0.7978845608028654f * (u + 0.044715f * u * u * u);
                    v0 = u / (1.0f + __expf(-2.0f * w));
                    u = v1;
                    w = 0.7978845608028654f * (u + 0.044715f * u * u * u);
                    v1 = u / (1.0f + __expf(-2.0f * w));
                }
                size_t off = (size_t)rw * N + cbase;
                if (Ch) {
                    if (cbase < N) {        // pair always inside (N mult of 8 here)
                        __half h0 = __float2half_rn(v0);
                        __half h1 = __float2half_rn(v1);
                        *(__half2*)(Ch + off) = __halves2half2(h0, h1);
                        if (Cl)
                            *(__half2*)(Cl + off) = __halves2half2(
                                __float2half_rn(v0 - __half2float(h0)),
                                __float2half_rn(v1 - __half2float(h1)));
                    }
                } else if (evenN) {
                    if (cbase < N) {
                        float2 o2 = make_float2(v0, v1);
                        if (res) {
                            float2 rv = *(const float2*)(res + off);
                            o2.x += rv.x; o2.y += rv.y;
                        }
                        *(float2*)(C + off) = o2;
                    }
                } else {
                    #pragma unroll
                    for (int cc = 0; cc < 2; cc++) {
                        int c = cbase + cc;
                        if (c < N) {
                            float v = cc ? v1 : v0;
                            if (res) v += res[off + cc];
                            C[off + cc] = v;
                        }
                    }
                }
            }
        }
    }

    if (lpart) {
        asm volatile("cp.async.wait_group 0;");
        __syncthreads();
        float* red = (float*)hsm;
        #pragma unroll
        for (int mt = 0; mt < 4; mt++) {
            #pragma unroll
            for (int hf = 0; hf < 2; hf++) {
                int wrow = wm * 64 + mt * 16 + lg + hf * 8;
                float vmax = -1e30f;
                #pragma unroll
                for (int nt = 0; nt < 4; nt++)
                    #pragma unroll
                    for (int cc = 0; cc < 2; cc++) {
                        int c = n0 + wn * 32 + nt * 8 + la * 2 + cc;
                        if (c < N) vmax = fmaxf(vmax, acc[mt][nt][hf * 2 + cc]);
                    }
                vmax = fmaxf(vmax, __shfl_xor_sync(0xffffffffu, vmax, 1));
                vmax = fmaxf(vmax, __shfl_xor_sync(0xffffffffu, vmax, 2));
                float vsum = 0.f;
                #pragma unroll
                for (int nt = 0; nt < 4; nt++)
                    #pragma unroll
                    for (int cc = 0; cc < 2; cc++) {
                        int c = n0 + wn * 32 + nt * 8 + la * 2 + cc;
                        if (c < N) vsum += __expf(acc[mt][nt][hf * 2 + cc] - vmax);
                    }
                vsum += __shfl_xor_sync(0xffffffffu, vsum, 1);
                vsum += __shfl_xor_sync(0xffffffffu, vsum, 2);
                if (la == 0) {
                    red[(wrow * 4 + wn) * 2]     = vmax;
                    red[(wrow * 4 + wn) * 2 + 1] = vsum;
                }
            }
        }
        __syncthreads();
        if (tid < 128) {
            float Mv = -1e30f, Sv = 0.f;
            #pragma unroll
            for (int w = 0; w < 4; w++) {
                float mi = red[(tid * 4 + w) * 2];
                float si = red[(tid * 4 + w) * 2 + 1];
                if (mi > Mv) { Sv = Sv * __expf(Mv - mi) + si; Mv = mi; }
                else         { Sv += si * __expf(mi - Mv); }
            }
            size_t pidx = ((size_t)(m0 + tid) * nbn + (n0 >> 7)) * 2;
            lpart[pidx]     = Mv;
            lpart[pidx + 1] = Sv;
        }
    }
}

// ---------------- flash attention v3: hi/lo fp16 inputs via cp.async --------
#define FQ 128
#define FATT_SMEM (49152 * 2)

__global__ __launch_bounds__(256)
void flash_attn(const __half* __restrict__ qh, const __half* __restrict__ ql,
                __half* __restrict__ y) {
    extern __shared__ __half fh[];
    __half *Ph = fh + 32768, *Pl = fh + 40960;

    int bh = blockIdx.y;
    int b = bh / H_, h = bh % H_;
    int q0 = blockIdx.x * FQ;
    int tid = threadIdx.x;
    int lane = tid & 31, wid = tid >> 5;
    int la = lane & 3, lg = lane >> 2;
    int l7 = lane & 7;

    unsigned sb = smem_u32(fh);
    unsigned sQh = sb, sQl = sb + 16384;
    unsigned sKh = sb + 32768, sKl = sb + 40960;
    unsigned sVh = sb + 49152, sVl = sb + 57344;
    unsigned sPh = sb + 65536, sPl = sb + 81920;

    // Q tiles: cp.async hi/lo straight into swizzled smem
    #pragma unroll
    for (int i = 0; i < 4; i++) {
        int id = tid + i * 256;                   // 0..1023 (128 rows x 8 chunks)
        int row = id >> 3, cc = id & 7;
        unsigned soff = (unsigned)((row * 64 + ((cc ^ (row & 7)) << 3)) * 2);
        size_t goff = (size_t)(b * T_ + q0 + row) * E3_ + h * D_ + cc * 8;
        CP16(sQh + soff, qh + goff);
        CP16(sQl + soff, ql + goff);
    }
    asm volatile("cp.async.commit_group;");
    asm volatile("cp.async.wait_group 0;");
    __syncthreads();

    int aCx = lane >> 4;
    unsigned qRowOff = (unsigned)((wid * 16 + l7 + ((lane >> 3) & 1) * 8) * 128);
    unsigned qfh[4][4], qfl[4][4];
    #pragma unroll
    for (int kc = 0; kc < 4; kc++) {
        unsigned cx = (unsigned)((((2 * kc + aCx) ^ l7)) << 4);
        LDSM_X4(qfh[kc][0], qfh[kc][1], qfh[kc][2], qfh[kc][3], sQh + qRowOff + cx);
        LDSM_X4(qfl[kc][0], qfl[kc][1], qfl[kc][2], qfl[kc][3], sQl + qRowOff + cx);
    }

    float m0r = -1e30f, m1r = -1e30f, l0r = 0.f, l1r = 0.f;
    float acc_o[8][4];
    #pragma unroll
    for (int i = 0; i < 8; i++)
        #pragma unroll
        for (int j = 0; j < 4; j++) acc_o[i][j] = 0.f;

    int row0g = q0 + wid * 16 + lg;
    int row1g = row0g + 8;
    int lastNeeded = (q0 + wid * 16 + 15) >> 6;
    int nkt = (q0 >> 6) + 2;

    for (int kt = 0; kt < nkt; kt++) {
        int k0 = kt << 6;
        __syncthreads();
        #pragma unroll
        for (int i = 0; i < 2; i++) {
            int id = tid + i * 256;               // 0..511 (64 rows x 8 chunks)
            int row = id >> 3, cc = id & 7;
            unsigned soff = (unsigned)((row * 64 + ((cc ^ (row & 7)) << 3)) * 2);
            size_t gk = (size_t)(b * T_ + k0 + row) * E3_ + E_ + h * D_ + cc * 8;
            size_t gv = gk + E_;
            CP16(sKh + soff, qh + gk);
            CP16(sKl + soff, ql + gk);
            CP16(sVh + soff, qh + gv);
            CP16(sVl + soff, ql + gv);
        }
        asm volatile("cp.async.commit_group;");
        asm volatile("cp.async.wait_group 0;");
        __syncthreads();
        if (kt > lastNeeded) continue;

        float s[8][4];
        #pragma unroll
        for (int i = 0; i < 8; i++)
            #pragma unroll
            for (int j = 0; j < 4; j++) s[i][j] = 0.f;

        int bCx = (lane >> 3) & 1;
        #pragma unroll
        for (int kc = 0; kc < 4; kc++) {
            unsigned kfh[8][2], kfl[8][2];
            #pragma unroll
            for (int p = 0; p < 4; p++) {
                unsigned rOff = (unsigned)((p * 16 + l7 + ((lane >> 4) << 3)) * 128);
                unsigned cx = (unsigned)((((2 * kc + bCx) ^ l7)) << 4);
                LDSM_X4(kfh[2*p][0], kfh[2*p][1], kfh[2*p+1][0], kfh[2*p+1][1],
                        sKh + rOff + cx);
                LDSM_X4(kfl[2*p][0], kfl[2*p][1], kfl[2*p+1][0], kfl[2*p+1][1],
                        sKl + rOff + cx);
            }
            #pragma unroll
            for (int nt = 0; nt < 8; nt++) {
                MMA_F16(s[nt], qfl[kc][0], qfl[kc][1], qfl[kc][2], qfl[kc][3],
                        kfh[nt][0], kfh[nt][1]);
                MMA_F16(s[nt], qfh[kc][0], qfh[kc][1], qfh[kc][2], qfh[kc][3],
                        kfl[nt][0], kfl[nt][1]);
                MMA_F16(s[nt], qfh[kc][0], qfh[kc][1], qfh[kc][2], qfh[kc][3],
                        kfh[nt][0], kfh[nt][1]);
            }
        }

        #pragma unroll
        for (int nt = 0; nt < 8; nt++) {
            int c0c = k0 + nt * 8 + 2 * la;
            s[nt][0] = (c0c     <= row0g) ? s[nt][0] * 0.125f : -1e30f;
            s[nt][1] = (c0c + 1 <= row0g) ? s[nt][1] * 0.125f : -1e30f;
            s[nt][2] = (c0c     <= row1g) ? s[nt][2] * 0.125f : -1e30f;
            s[nt][3] = (c0c + 1 <= row1g) ? s[nt][3] * 0.125f : -1e30f;
        }

        float mx0 = -1e30f, mx1 = -1e30f;
        #pragma unroll
        for (int nt = 0; nt < 8; nt++) {
            mx0 = fmaxf(mx0, fmaxf(s[nt][0], s[nt][1]));
            mx1 = fmaxf(mx1, fmaxf(s[nt][2], s[nt][3]));
        }
        mx0 = fmaxf(mx0, __shfl_xor_sync(0xffffffffu, mx0, 1));
        mx0 = fmaxf(mx0, __shfl_xor_sync(0xffffffffu, mx0, 2));
        mx1 = fmaxf(mx1, __shfl_xor_sync(0xffffffffu, mx1, 1));
        mx1 = fmaxf(mx1, __shfl_xor_sync(0xffffffffu, mx1, 2));
        float m0n = fmaxf(m0r, mx0), m1n = fmaxf(m1r, mx1);
        float a0 = __expf(m0r - m0n), a1 = __expf(m1r - m1n);
        m0r = m0n; m1r = m1n;

        float ts0 = 0.f, ts1 = 0.f;
        #pragma unroll
        for (int nt = 0; nt < 8; nt++) {
            s[nt][0] = __expf(s[nt][0] - m0n);
            s[nt][1] = __expf(s[nt][1] - m0n);
            s[nt][2] = __expf(s[nt][2] - m1n);
            s[nt][3] = __expf(s[nt][3] - m1n);
            ts0 += s[nt][0] + s[nt][1];
            ts1 += s[nt][2] + s[nt][3];
        }
        ts0 += __shfl_xor_sync(0xffffffffu, ts0, 1);
        ts0 += __shfl_xor_sync(0xffffffffu, ts0, 2);
        ts1 += __shfl_xor_sync(0xffffffffu, ts1, 1);
        ts1 += __shfl_xor_sync(0xffffffffu, ts1, 2);
        l0r = l0r * a0 + ts0;
        l1r = l1r * a1 + ts1;
        #pragma unroll
        for (int nt = 0; nt < 8; nt++) {
            acc_o[nt][0] *= a0; acc_o[nt][1] *= a0;
            acc_o[nt][2] *= a1; acc_o[nt][3] *= a1;
        }

        __half* Pwh = Ph + wid * 1024;
        __half* Pwl = Pl + wid * 1024;
        #pragma unroll
        for (int nt = 0; nt < 8; nt++) {
            int ph0 = lg * 64 + ((nt ^ (lg & 7)) << 3) + 2 * la;
            __half h0 = __float2half_rn(s[nt][0]), h1 = __float2half_rn(s[nt][1]);
            *(__half2*)(Pwh + ph0) = __halves2half2(h0, h1);
            *(__half2*)(Pwl + ph0) = __halves2half2(
                __float2half_rn(s[nt][0] - __half2float(h0)),
                __float2half_rn(s[nt][1] - __half2float(h1)));
            int ph1 = ph0 + 8 * 64;
            __half h2 = __float2half_rn(s[nt][2]), h3 = __float2half_rn(s[nt][3]);
            *(__half2*)(Pwh + ph1) = __halves2half2(h2, h3);
            *(__half2*)(Pwl + ph1) = __halves2half2(
                __float2half_rn(s[nt][2] - __half2float(h2)),
                __float2half_rn(s[nt][3] - __half2float(h3)));
        }
        __syncwarp();

        unsigned pRowOff = (unsigned)((l7 + ((lane >> 3) & 1) * 8) * 128)
                         + (unsigned)(wid * 2048);
        #pragma unroll
        for (int kc = 0; kc < 4; kc++) {
            unsigned pfh[4], pfl[4];
            unsigned cx = (unsigned)((((2 * kc + aCx) ^ l7)) << 4);
            LDSM_X4(pfh[0], pfh[1], pfh[2], pfh[3], sPh + pRowOff + cx);
            LDSM_X4(pfl[0], pfl[1], pfl[2], pfl[3], sPl + pRowOff + cx);
            unsigned vfh[8][2], vfl[8][2];
            int vrow = kc * 16 + l7 + ((lane >> 3) & 1) * 8;
            #pragma unroll
            for (int pd = 0; pd < 4; pd++) {
                int dgc = 2 * pd + (lane >> 4);
                unsigned voff = (unsigned)(vrow * 128 + (((dgc) ^ (vrow & 7)) << 4));
                LDSM_X4T(vfh[2*pd][0], vfh[2*pd][1], vfh[2*pd+1][0], vfh[2*pd+1][1],
                         sVh + voff);
                LDSM_X4T(vfl[2*pd][0], vfl[2*pd][1], vfl[2*pd+1][0], vfl[2*pd+1][1],
                         sVl + voff);
            }
            #pragma unroll
            for (int nt = 0; nt < 8; nt++) {
                MMA_F16(acc_o[nt], pfl[0], pfl[1], pfl[2], pfl[3],
                        vfh[nt][0], vfh[nt][1]);
                MMA_F16(acc_o[nt], pfh[0], pfh[1], pfh[2], pfh[3],
                        vfl[nt][0], vfl[nt][1]);
                MMA_F16(acc_o[nt], pfh[0], pfh[1], pfh[2], pfh[3],
                        vfh[nt][0], vfh[nt][1]);
            }
        }
    }

    float inv0 = 1.0f / l0r, inv1 = 1.0f / l1r;
    size_t o0 = (size_t)(b * T_ + q0 + wid * 16 + lg) * E_ + h * D_;
    size_t o1 = o0 + 8 * E_;
    #pragma unroll
    for (int nt = 0; nt < 8; nt++) {
        int c = nt * 8 + 2 * la;
        *(__half2*)(y + o0 + c) = __floats2half2_rn(acc_o[nt][0] * inv0,
                                                    acc_o[nt][1] * inv0);
        *(__half2*)(y + o1 + c) = __floats2half2_rn(acc_o[nt][2] * inv1,
                                                    acc_o[nt][3] * inv1);
    }
}

// ---------------- loss: combine per-block partials (one warp per row) -------
__global__ __launch_bounds__(256)
void loss_reduce(const float* __restrict__ logits,
                 const int* __restrict__ targets) {
    int gid = blockIdx.x * 8 + (threadIdx.x >> 5);
    int lane = threadIdx.x & 31;
    if (gid >= B_ * (T_ - 1)) return;
    int b = gid / (T_ - 1), t = gid % (T_ - 1);
    int row = b * T_ + t;
    float Mv = -1e30f, Sv = 0.f;
    for (int i = lane; i < NBN_V; i += 32) {
        float mi = g_lpart[((size_t)row * NBN_V + i) * 2];
        float si = g_lpart[((size_t)row * NBN_V + i) * 2 + 1];
        if (mi > Mv) { Sv = Sv * __expf(Mv - mi) + si; Mv = mi; }
        else         { Sv += si * __expf(mi - Mv); }
    }
    #pragma unroll
    for (int o = 16; o; o >>= 1) {
        float m2 = __shfl_down_sync(0xffffffffu, Mv, o);
        float s2 = __shfl_down_sync(0xffffffffu, Sv, o);
        float mN = fmaxf(Mv, m2);
        Sv = Sv * __expf(Mv - mN) + s2 * __expf(m2 - mN);
        Mv = mN;
    }
    if (lane == 0) {
        int label = targets[row + 1];
        g_logp[gid] = logits[(size_t)row * V_ + label] - Mv - logf(Sv);
    }
}

__global__ void loss_final(float* __restrict__ out, long long pos) {
    __shared__ float red[32];
    float s = 0.f;
    for (int i = threadIdx.x; i < B_ * (T_ - 1); i += 256) s += g_logp[i];
    s = blockReduceSum(s, red);
    if (threadIdx.x == 0) out[pos] = -s / (float)(B_ * (T_ - 1));
}

// ---------------- driver ----------------------------------------------------
static inline int gemm_grid(int N) {
    return (M_ >> 7) * ((N + 127) >> 7);
}

static inline void cvt_weights(const float* src, __half* dst, long long n) {
    int n4 = (int)(n >> 2);
    cvt_f16_kernel<<<(n4 + 255) / 256, 256>>>(
        (const float4*)src, (__half2*)dst, n4);
}

extern "C" void kernel_launch(void* const* d_in, const int* in_sizes, int n_in,
                              void* d_out, int out_size) {
    const int*   idx     = (const int*)  d_in[0];
    const int*   targets = (const int*)  d_in[1];
    const float* wte     = (const float*)d_in[2];
    const float* wpe     = (const float*)d_in[3];
    const float* ln1_w   = (const float*)d_in[4];
    const float* ln1_b   = (const float*)d_in[5];
    const float* attn_w  = (const float*)d_in[6];
    const float* attn_b  = (const float*)d_in[7];
    const float* proj_w  = (const float*)d_in[8];
    const float* proj_b  = (const float*)d_in[9];
    const float* ln2_w   = (const float*)d_in[10];
    const float* ln2_b   = (const float*)d_in[11];
    const float* fc_w    = (const float*)d_in[12];
    const float* fc_b    = (const float*)d_in[13];
    const float* out_w   = (const float*)d_in[14];
    const float* out_b   = (const float*)d_in[15];
    const float* lnf_w   = (const float*)d_in[16];
    const float* lnf_b   = (const float*)d_in[17];
    float* out = (float*)d_out;

    float *x, *lpart;
    __half *h, *qh, *ql, *y, *fc;
    __half *w_attn, *w_proj, *w_fc, *w_out, *w_wte;
    cudaGetSymbolAddress((void**)&x,   g_x);
    cudaGetSymbolAddress((void**)&h,   g_h);
    cudaGetSymbolAddress((void**)&qh,  g_qh);
    cudaGetSymbolAddress((void**)&ql,  g_ql);
    cudaGetSymbolAddress((void**)&y,   g_y);
    cudaGetSymbolAddress((void**)&fc,  g_fc);
    cudaGetSymbolAddress((void**)&lpart, g_lpart);
    cudaGetSymbolAddress((void**)&w_attn, g_w_attn);
    cudaGetSymbolAddress((void**)&w_proj, g_w_proj);
    cudaGetSymbolAddress((void**)&w_fc,   g_w_fc);
    cudaGetSymbolAddress((void**)&w_out,  g_w_out);
    cudaGetSymbolAddress((void**)&w_wte,  g_w_wte);

    cudaFuncSetAttribute(flash_attn,
                         cudaFuncAttributeMaxDynamicSharedMemorySize, FATT_SMEM);
    cudaFuncSetAttribute(gemm_f16,
                         cudaFuncAttributeMaxDynamicSharedMemorySize, GEMM_SMEM);

    cvt_weights(attn_w, w_attn, (long long)L_ * E3_ * E_);
    cvt_weights(proj_w, w_proj, (long long)L_ * E_ * E_);
    cvt_weights(fc_w,   w_fc,   (long long)L_ * E4_ * E_);
    cvt_weights(out_w,  w_out,  (long long)L_ * E_ * E4_);
    cvt_weights(wte,    w_wte,  (long long)V_ * E_);

    embed_kernel<<<(M_ * E_) / 256, 256>>>(idx, wte, wpe);

    for (int l = 0; l < L_; l++) {
        ln_kernel<<<M_ / 8, 256>>>(x, ln1_w + (size_t)l * E_, ln1_b + (size_t)l * E_, h);
        gemm_f16<<<gemm_grid(E3_), 256, GEMM_SMEM>>>(
            h, w_attn + (size_t)l * E3_ * E_, attn_b + (size_t)l * E3_,
            nullptr, nullptr, qh, ql, nullptr, M_, E3_, E_, 0);
        flash_attn<<<dim3(T_ / FQ, B_ * H_), 256, FATT_SMEM>>>(qh, ql, y);
        gemm_f16<<<gemm_grid(E_), 256, GEMM_SMEM>>>(
            y, w_proj + (size_t)l * E_ * E_, proj_b + (size_t)l * E_,
            x, x, nullptr, nullptr, nullptr, M_, E_, E_, 0);
        ln_kernel<<<M_ / 8, 256>>>(x, ln2_w + (size_t)l * E_, ln2_b + (size_t)l * E_, h);
        gemm_f16<<<gemm_grid(E4_), 256, GEMM_SMEM>>>(
            h, w_fc + (size_t)l * E4_ * E_, fc_b + (size_t)l * E4_,
            nullptr, nullptr, fc, nullptr, nullptr, M_, E4_, E_, 1);
        gemm_f16<<<gemm_grid(E_), 256, GEMM_SMEM>>>(
            fc, w_out + (size_t)l * E_ * E4_, out_b + (size_t)l * E_,
            x, x, nullptr, nullptr, nullptr, M_, E_, E4_, 0);
    }

    ln_kernel<<<M_ / 8, 256>>>(x, lnf_w, lnf_b, h);
    gemm_f16<<<gemm_grid(V_), 256, GEMM_SMEM>>>(
        h, w_wte, nullptr, nullptr, out, nullptr, nullptr, lpart, M_, V_, E_, 0);

    loss_reduce<<<(B_ * (T_ - 1) + 7) / 8, 256>>>(out, targets);
    long long pos = (long long)M_ * V_;
    if (pos < (long long)out_size)
        loss_final<<<1, 256>>>(out, pos);
}